// round 2
// baseline (speedup 1.0000x reference)
#include <cuda_runtime.h>
#include <math.h>

#define N_TOK 2304   // 48*48
#define C_DIM 256
#define HID   512    // 8 heads * 64

// Scratch (no allocations allowed): qkv = [b][1536][N], att out = [b][512][N]
__device__ float g_qkv[2][1536][N_TOK];
__device__ float g_att[2][512][N_TOK];

// ---------------------------------------------------------------------------
// Generic tiled GEMM: C[M,N] = W[M,K] @ X[K,N] (+ bias), batched over blockIdx.z
// 64x64 tile, 256 threads, 4x4 per thread, K-tile = 16.
// ---------------------------------------------------------------------------
__global__ __launch_bounds__(256) void gemm_kernel(
    const float* __restrict__ W,
    const float* __restrict__ Xb,
    float* __restrict__ Cb,
    const float* __restrict__ bias,
    int M, int N, int K,
    long xStride, long cStride)
{
    __shared__ float Ws[16][65];   // [kk][ii], padded vs bank conflicts
    __shared__ float Xs[16][64];   // [kk][jj]

    const float* X = Xb + (long)blockIdx.z * xStride;
    float* C = Cb + (long)blockIdx.z * cStride;
    const int by = blockIdx.y * 64;
    const int bx = blockIdx.x * 64;
    const int t  = threadIdx.x;
    const int tx = t & 15, ty = t >> 4;

    float acc[4][4] = {};

    for (int kt = 0; kt < K; kt += 16) {
#pragma unroll
        for (int l = 0; l < 4; l++) {
            int idx = t + l * 256;
            int ii = idx >> 4, kk = idx & 15;
            Ws[kk][ii] = W[(long)(by + ii) * K + kt + kk];
        }
#pragma unroll
        for (int l = 0; l < 4; l++) {
            int idx = t + l * 256;
            int kk = idx >> 6, jj = idx & 63;
            Xs[kk][jj] = X[(long)(kt + kk) * N + bx + jj];
        }
        __syncthreads();
#pragma unroll
        for (int kk = 0; kk < 16; kk++) {
            float a0 = Ws[kk][ty * 4 + 0];
            float a1 = Ws[kk][ty * 4 + 1];
            float a2 = Ws[kk][ty * 4 + 2];
            float a3 = Ws[kk][ty * 4 + 3];
            float4 bv = *(const float4*)&Xs[kk][tx * 4];
            acc[0][0] += a0 * bv.x; acc[0][1] += a0 * bv.y; acc[0][2] += a0 * bv.z; acc[0][3] += a0 * bv.w;
            acc[1][0] += a1 * bv.x; acc[1][1] += a1 * bv.y; acc[1][2] += a1 * bv.z; acc[1][3] += a1 * bv.w;
            acc[2][0] += a2 * bv.x; acc[2][1] += a2 * bv.y; acc[2][2] += a2 * bv.z; acc[2][3] += a2 * bv.w;
            acc[3][0] += a3 * bv.x; acc[3][1] += a3 * bv.y; acc[3][2] += a3 * bv.z; acc[3][3] += a3 * bv.w;
        }
        __syncthreads();
    }

#pragma unroll
    for (int i = 0; i < 4; i++) {
        float bb = bias ? bias[by + ty * 4 + i] : 0.0f;
        float4 o = make_float4(acc[i][0] + bb, acc[i][1] + bb, acc[i][2] + bb, acc[i][3] + bb);
        *(float4*)&C[(long)(by + ty * 4 + i) * N + bx + tx * 4] = o;
    }
}

// ---------------------------------------------------------------------------
// Per-(b, q/k, h, d) L2 normalization over the token axis (in place).
// grid = 2048 blocks (b*1024 + row), row 0..511 = q rows, 512..1023 = k rows.
// ---------------------------------------------------------------------------
__global__ __launch_bounds__(256) void normalize_kernel()
{
    const int b   = blockIdx.x >> 10;
    const int row = blockIdx.x & 1023;
    float* p = g_qkv[b][row];
    const int t = threadIdx.x;

    float ss = 0.0f;
    for (int i = t; i < N_TOK; i += 256) { float v = p[i]; ss += v * v; }

    __shared__ float red[256];
    red[t] = ss;
    __syncthreads();
    for (int s = 128; s > 0; s >>= 1) {
        if (t < s) red[t] += red[t + s];
        __syncthreads();
    }
    __shared__ float sinv;
    if (t == 0) sinv = 1.0f / fmaxf(sqrtf(red[0]), 1e-12f);
    __syncthreads();
    const float inv = sinv;
    for (int i = t; i < N_TOK; i += 256) p[i] *= inv;
}

// ---------------------------------------------------------------------------
// Fused attention, flash style. One block = 64 query tokens of one (b,h).
// Q tile (64d x 64n) resident in smem; stream K/V tiles over m; softmax
// without max-subtraction (logits are tiny: q,k are L2-normalized over tokens).
// P is stored TRANSPOSED (m-major) so both tile-GEMMs read the contraction
// index as the smem row and vectorize the free index -> conflict-free LDS.
// smem = 4 * 64*64 floats = 64 KB (dynamic).
// ---------------------------------------------------------------------------
__global__ __launch_bounds__(256) void attn_kernel()
{
    extern __shared__ float sm[];
    float* Qs = sm;            // [d][n]
    float* Ks = sm + 4096;     // [d][m]
    float* Vs = sm + 8192;     // [d][m]
    float* Ps = sm + 12288;    // [m][n]  (exp(S) transposed)

    const int bh = blockIdx.y;
    const int b = bh >> 3, h = bh & 7;
    const int nt = blockIdx.x * 64;
    const float* qg = g_qkv[b][h * 64];
    const float* kg = g_qkv[b][512 + h * 64];
    const float* vg = g_qkv[b][1024 + h * 64];
    float* og = g_att[b][h * 64];

    const int t = threadIdx.x, tx = t & 15, ty = t >> 4;

#pragma unroll
    for (int l = 0; l < 16; l++) {
        int idx = t + l * 256;
        int d = idx >> 6, nl = idx & 63;
        Qs[d * 64 + nl] = qg[(long)d * N_TOK + nt + nl];
    }

    float oacc[4][4] = {};            // [d = 4ty+i][n = 4tx+j]
    float rs = 0.0f;                  // partial softmax denominator
    const int rn = t & 63, rq = t >> 6;   // thread sums Ps[16*rq + mm][rn]

    for (int mt = 0; mt < N_TOK; mt += 64) {
        __syncthreads();  // prior iteration done reading Ks/Vs/Ps
#pragma unroll
        for (int l = 0; l < 16; l++) {
            int idx = t + l * 256;
            int d = idx >> 6, ml = idx & 63;
            Ks[d * 64 + ml] = kg[(long)d * N_TOK + mt + ml];
            Vs[d * 64 + ml] = vg[(long)d * N_TOK + mt + ml];
        }
        __syncthreads();

        // S^T fragment: rows m = 4ty+i, cols n = 4tx+j
        float s[4][4] = {};
#pragma unroll
        for (int d = 0; d < 64; d++) {
            float a0 = Ks[d * 64 + ty * 4 + 0];
            float a1 = Ks[d * 64 + ty * 4 + 1];
            float a2 = Ks[d * 64 + ty * 4 + 2];
            float a3 = Ks[d * 64 + ty * 4 + 3];
            float4 bv = *(const float4*)&Qs[d * 64 + tx * 4];
            s[0][0] += a0 * bv.x; s[0][1] += a0 * bv.y; s[0][2] += a0 * bv.z; s[0][3] += a0 * bv.w;
            s[1][0] += a1 * bv.x; s[1][1] += a1 * bv.y; s[1][2] += a1 * bv.z; s[1][3] += a1 * bv.w;
            s[2][0] += a2 * bv.x; s[2][1] += a2 * bv.y; s[2][2] += a2 * bv.z; s[2][3] += a2 * bv.w;
            s[3][0] += a3 * bv.x; s[3][1] += a3 * bv.y; s[3][2] += a3 * bv.z; s[3][3] += a3 * bv.w;
        }
        // exp + transposed store (vectorized over n, conflict-free)
#pragma unroll
        for (int i = 0; i < 4; i++) {
            float4 e;
            e.x = __expf(s[i][0]); e.y = __expf(s[i][1]);
            e.z = __expf(s[i][2]); e.w = __expf(s[i][3]);
            *(float4*)&Ps[(ty * 4 + i) * 64 + tx * 4] = e;
        }
        __syncthreads();

        // softmax denominator partial: sum over m of Ps[m][rn]
#pragma unroll
        for (int mm = 0; mm < 16; mm++) rs += Ps[(rq * 16 + mm) * 64 + rn];

        // O accumulation: oacc[d][n] += sum_m Vs[d][m] * Ps[m][n]
#pragma unroll
        for (int m = 0; m < 64; m++) {
            float a0 = Vs[(ty * 4 + 0) * 64 + m];
            float a1 = Vs[(ty * 4 + 1) * 64 + m];
            float a2 = Vs[(ty * 4 + 2) * 64 + m];
            float a3 = Vs[(ty * 4 + 3) * 64 + m];
            float4 bv = *(const float4*)&Ps[m * 64 + tx * 4];
            oacc[0][0] += a0 * bv.x; oacc[0][1] += a0 * bv.y; oacc[0][2] += a0 * bv.z; oacc[0][3] += a0 * bv.w;
            oacc[1][0] += a1 * bv.x; oacc[1][1] += a1 * bv.y; oacc[1][2] += a1 * bv.z; oacc[1][3] += a1 * bv.w;
            oacc[2][0] += a2 * bv.x; oacc[2][1] += a2 * bv.y; oacc[2][2] += a2 * bv.z; oacc[2][3] += a2 * bv.w;
            oacc[3][0] += a3 * bv.x; oacc[3][1] += a3 * bv.y; oacc[3][2] += a3 * bv.z; oacc[3][3] += a3 * bv.w;
        }
    }

    // reduce the 4 denominator partials per token (reuse Ps as scratch)
    __syncthreads();
    Ps[rn * 4 + rq] = rs;
    __syncthreads();
    float inv[4];
#pragma unroll
    for (int j = 0; j < 4; j++) {
        int n = tx * 4 + j;
        inv[j] = 1.0f / (Ps[n * 4 + 0] + Ps[n * 4 + 1] + Ps[n * 4 + 2] + Ps[n * 4 + 3]);
    }
#pragma unroll
    for (int i = 0; i < 4; i++) {
        float4 o = make_float4(oacc[i][0] * inv[0], oacc[i][1] * inv[1],
                               oacc[i][2] * inv[2], oacc[i][3] * inv[3]);
        *(float4*)&og[(long)(ty * 4 + i) * N_TOK + nt + tx * 4] = o;
    }
}

// ---------------------------------------------------------------------------
extern "C" void kernel_launch(void* const* d_in, const int* in_sizes, int n_in,
                              void* d_out, int out_size)
{
    const float* x      = (const float*)d_in[0];  // [2,256,48,48]
    const float* w_qkv  = (const float*)d_in[1];  // [1536,256]
    const float* w_proj = (const float*)d_in[2];  // [256,512]
    const float* b_proj = (const float*)d_in[3];  // [256]
    float* y = (float*)d_out;                     // [2,256,48,48]

    float* qkv_ptr = nullptr;
    float* att_ptr = nullptr;
    cudaGetSymbolAddress((void**)&qkv_ptr, g_qkv);
    cudaGetSymbolAddress((void**)&att_ptr, g_att);

    cudaFuncSetAttribute(attn_kernel, cudaFuncAttributeMaxDynamicSharedMemorySize, 65536);

    // 1) QKV projection: per batch C[1536, 2304] = w_qkv[1536,256] @ x[b][256,2304]
    gemm_kernel<<<dim3(N_TOK / 64, 1536 / 64, 2), 256>>>(
        w_qkv, x, qkv_ptr, nullptr, 1536, N_TOK, C_DIM,
        (long)C_DIM * N_TOK, (long)1536 * N_TOK);

    // 2) L2 normalize q and k rows over tokens (in place)
    normalize_kernel<<<2048, 256>>>();

    // 3) Fused attention -> g_att
    attn_kernel<<<dim3(N_TOK / 64, 16), 256, 65536>>>();

    // 4) Output projection + bias: y[b][256,2304] = w_proj @ att[b] + b_proj
    gemm_kernel<<<dim3(N_TOK / 64, C_DIM / 64, 2), 256>>>(
        w_proj, att_ptr, y, b_proj, C_DIM, N_TOK, HID,
        (long)HID * N_TOK, (long)C_DIM * N_TOK);
}

// round 3
// speedup vs baseline: 1.2878x; 1.2878x over previous
#include <cuda_runtime.h>
#include <math.h>

#define N_TOK 2304   // 48*48
#define C_DIM 256
#define HID   512    // 8 heads * 64

// Scratch (no allocations allowed): qkv = [b][1536][N], att out = [b][512][N]
__device__ float g_qkv[2][1536][N_TOK];
__device__ float g_att[2][512][N_TOK];

// ---- packed f32x2 helpers ---------------------------------------------------
__device__ __forceinline__ unsigned long long pack2(float lo, float hi) {
    unsigned long long r;
    asm("mov.b64 %0, {%1,%2};" : "=l"(r) : "f"(lo), "f"(hi));
    return r;
}
__device__ __forceinline__ void unpack2(unsigned long long v, float& lo, float& hi) {
    asm("mov.b64 {%0,%1}, %2;" : "=f"(lo), "=f"(hi) : "l"(v));
}
__device__ __forceinline__ void ffma2(unsigned long long& d,
                                      unsigned long long a, unsigned long long b) {
    asm("fma.rn.f32x2 %0, %1, %2, %3;" : "=l"(d) : "l"(a), "l"(b), "l"(d));
}

// ---------------------------------------------------------------------------
// Tiled GEMM via packed FFMA2: C[M,N] = W[M,K] @ X[K,N] (+bias), z = batch.
// Block tile 128(M) x 64(N), K-tile 16, 256 threads, 8x4 per thread.
// W is staged in smem DUPLICATED as (w,w) 64-bit pairs -> LDS128 gives two
// broadcast pairs; X float4 reinterpreted as two packed j-pairs.
// ---------------------------------------------------------------------------
__global__ __launch_bounds__(256) void gemm_kernel(
    const float* __restrict__ W,
    const float* __restrict__ Xb,
    float* __restrict__ Cb,
    const float* __restrict__ bias,
    int M, int N, int K,
    long xStride, long cStride)
{
    __shared__ unsigned long long Ws2[16][130];  // [kk][ii] dup pairs, padded
    __shared__ float Xs[16][64];                 // [kk][jj]

    const float* X = Xb + (long)blockIdx.z * xStride;
    float* C = Cb + (long)blockIdx.z * cStride;
    const int by = blockIdx.y * 128;
    const int bx = blockIdx.x * 64;
    const int t  = threadIdx.x;
    const int tx = t & 15, ty = t >> 4;

    unsigned long long acc[8][2] = {};   // rows i=8*ty+0..7, col-pairs jp

    for (int kt = 0; kt < K; kt += 16) {
#pragma unroll
        for (int l = 0; l < 8; l++) {
            int idx = t + l * 256;
            int ii = idx >> 4, kk = idx & 15;
            float w = W[(long)(by + ii) * K + kt + kk];
            Ws2[kk][ii] = pack2(w, w);
        }
#pragma unroll
        for (int l = 0; l < 4; l++) {
            int idx = t + l * 256;
            int kk = idx >> 6, jj = idx & 63;
            Xs[kk][jj] = X[(long)(kt + kk) * N + bx + jj];
        }
        __syncthreads();
#pragma unroll
        for (int kk = 0; kk < 16; kk++) {
            unsigned long long a[8];
            *(ulonglong2*)&a[0] = *(const ulonglong2*)&Ws2[kk][ty * 8 + 0];
            *(ulonglong2*)&a[2] = *(const ulonglong2*)&Ws2[kk][ty * 8 + 2];
            *(ulonglong2*)&a[4] = *(const ulonglong2*)&Ws2[kk][ty * 8 + 4];
            *(ulonglong2*)&a[6] = *(const ulonglong2*)&Ws2[kk][ty * 8 + 6];
            ulonglong2 b = *(const ulonglong2*)&Xs[kk][tx * 4];
#pragma unroll
            for (int i = 0; i < 8; i++) {
                ffma2(acc[i][0], a[i], b.x);
                ffma2(acc[i][1], a[i], b.y);
            }
        }
        __syncthreads();
    }

#pragma unroll
    for (int i = 0; i < 8; i++) {
        int row = by + ty * 8 + i;
        float bb = bias ? bias[row] : 0.0f;
        float o0, o1, o2, o3;
        unpack2(acc[i][0], o0, o1);
        unpack2(acc[i][1], o2, o3);
        float4 o = make_float4(o0 + bb, o1 + bb, o2 + bb, o3 + bb);
        *(float4*)&C[(long)row * N + bx + tx * 4] = o;
    }
}

// ---------------------------------------------------------------------------
// Per-(b, q/k, h, d) L2 normalization over the token axis (in place).
// ---------------------------------------------------------------------------
__global__ __launch_bounds__(256) void normalize_kernel()
{
    const int b   = blockIdx.x >> 10;
    const int row = blockIdx.x & 1023;
    float* p = g_qkv[b][row];
    const int t = threadIdx.x;

    float ss = 0.0f;
    for (int i = t; i < N_TOK; i += 256) { float v = p[i]; ss += v * v; }

    __shared__ float red[256];
    red[t] = ss;
    __syncthreads();
    for (int s = 128; s > 0; s >>= 1) {
        if (t < s) red[t] += red[t + s];
        __syncthreads();
    }
    __shared__ float sinv;
    if (t == 0) sinv = 1.0f / fmaxf(sqrtf(red[0]), 1e-12f);
    __syncthreads();
    const float inv = sinv;
    for (int i = t; i < N_TOK; i += 256) p[i] *= inv;
}

// ---------------------------------------------------------------------------
// Fused flash attention with packed FFMA2.
// One block = 64 query tokens of one (b,h). Q tile resident; stream K/V.
// K staged duplicated as (k,k) pairs [d][m]; V duplicated [m][d] (padded 66).
// P stored transposed (m-major) so both inner GEMMs read contraction as rows.
// smem: Ks2 32KB + Vs2 33KB + Qs 16KB + Ps 16KB ~= 96.5KB -> 2 blocks/SM.
// ---------------------------------------------------------------------------
__global__ __launch_bounds__(256) void attn_kernel()
{
    extern __shared__ char smraw[];
    unsigned long long* Ks2 = (unsigned long long*)smraw;          // [d][m]   64*64
    unsigned long long* Vs2 = Ks2 + 4096;                          // [m][d+pad] 64*66
    float* Qs = (float*)(Vs2 + 64 * 66);                           // [d][n]   64*64
    float* Ps = Qs + 4096;                                         // [m][n]   64*64

    const int bh = blockIdx.y;
    const int b = bh >> 3, h = bh & 7;
    const int nt = blockIdx.x * 64;
    const float* qg = g_qkv[b][h * 64];
    const float* kg = g_qkv[b][512 + h * 64];
    const float* vg = g_qkv[b][1024 + h * 64];
    float* og = g_att[b][h * 64];

    const int t = threadIdx.x, tx = t & 15, ty = t >> 4;

#pragma unroll
    for (int l = 0; l < 16; l++) {
        int idx = t + l * 256;
        int d = idx >> 6, nl = idx & 63;
        Qs[d * 64 + nl] = qg[(long)d * N_TOK + nt + nl];
    }

    unsigned long long oacc[4][2] = {};   // [d = 4ty+i][n-pair jp]
    float rs = 0.0f;                      // partial softmax denominator
    const int rn = t & 63, rq = t >> 6;   // thread sums Ps[16*rq + mm][rn]

    for (int mt = 0; mt < N_TOK; mt += 64) {
        __syncthreads();  // prior iteration done reading Ks2/Vs2/Ps
#pragma unroll
        for (int l = 0; l < 16; l++) {
            int idx = t + l * 256;
            int d = idx >> 6, ml = idx & 63;
            float kv = kg[(long)d * N_TOK + mt + ml];
            float vv = vg[(long)d * N_TOK + mt + ml];
            Ks2[d * 64 + ml] = pack2(kv, kv);
            Vs2[ml * 66 + d] = pack2(vv, vv);
        }
        __syncthreads();

        // S^T fragment: rows m = 4ty+i (broadcast from dup-K), cols n packed
        unsigned long long s2[4][2] = {};
#pragma unroll
        for (int d = 0; d < 64; d++) {
            unsigned long long a[4];
            *(ulonglong2*)&a[0] = *(const ulonglong2*)&Ks2[d * 64 + ty * 4 + 0];
            *(ulonglong2*)&a[2] = *(const ulonglong2*)&Ks2[d * 64 + ty * 4 + 2];
            ulonglong2 bq = *(const ulonglong2*)&Qs[d * 64 + tx * 4];
#pragma unroll
            for (int i = 0; i < 4; i++) {
                ffma2(s2[i][0], a[i], bq.x);
                ffma2(s2[i][1], a[i], bq.y);
            }
        }
        // exp + transposed store (vectorized over n)
#pragma unroll
        for (int i = 0; i < 4; i++) {
            float x0, x1, x2, x3;
            unpack2(s2[i][0], x0, x1);
            unpack2(s2[i][1], x2, x3);
            float4 e = make_float4(__expf(x0), __expf(x1), __expf(x2), __expf(x3));
            *(float4*)&Ps[(ty * 4 + i) * 64 + tx * 4] = e;
        }
        __syncthreads();

        // softmax denominator partial: sum over m of Ps[m][rn]
#pragma unroll
        for (int mm = 0; mm < 16; mm++) rs += Ps[(rq * 16 + mm) * 64 + rn];

        // O accumulation: oacc[d][n] += V[d][m] * P[m][n]  (V broadcast pairs)
#pragma unroll
        for (int m = 0; m < 64; m++) {
            unsigned long long v[4];
            *(ulonglong2*)&v[0] = *(const ulonglong2*)&Vs2[m * 66 + ty * 4 + 0];
            *(ulonglong2*)&v[2] = *(const ulonglong2*)&Vs2[m * 66 + ty * 4 + 2];
            ulonglong2 p = *(const ulonglong2*)&Ps[m * 64 + tx * 4];
#pragma unroll
            for (int i = 0; i < 4; i++) {
                ffma2(oacc[i][0], v[i], p.x);
                ffma2(oacc[i][1], v[i], p.y);
            }
        }
    }

    // reduce the 4 denominator partials per token (reuse Ps as scratch)
    __syncthreads();
    Ps[rn * 4 + rq] = rs;
    __syncthreads();
    float inv[4];
#pragma unroll
    for (int j = 0; j < 4; j++) {
        int n = tx * 4 + j;
        inv[j] = 1.0f / (Ps[n * 4 + 0] + Ps[n * 4 + 1] + Ps[n * 4 + 2] + Ps[n * 4 + 3]);
    }
#pragma unroll
    for (int i = 0; i < 4; i++) {
        float o0, o1, o2, o3;
        unpack2(oacc[i][0], o0, o1);
        unpack2(oacc[i][1], o2, o3);
        float4 o = make_float4(o0 * inv[0], o1 * inv[1], o2 * inv[2], o3 * inv[3]);
        *(float4*)&og[(long)(ty * 4 + i) * N_TOK + nt + tx * 4] = o;
    }
}

// ---------------------------------------------------------------------------
extern "C" void kernel_launch(void* const* d_in, const int* in_sizes, int n_in,
                              void* d_out, int out_size)
{
    const float* x      = (const float*)d_in[0];  // [2,256,48,48]
    const float* w_qkv  = (const float*)d_in[1];  // [1536,256]
    const float* w_proj = (const float*)d_in[2];  // [256,512]
    const float* b_proj = (const float*)d_in[3];  // [256]
    float* y = (float*)d_out;                     // [2,256,48,48]

    float* qkv_ptr = nullptr;
    float* att_ptr = nullptr;
    cudaGetSymbolAddress((void**)&qkv_ptr, g_qkv);
    cudaGetSymbolAddress((void**)&att_ptr, g_att);

    const int attn_smem = (4096 + 64 * 66) * 8 + (4096 + 4096) * 4;  // ~96.5KB
    cudaFuncSetAttribute(attn_kernel, cudaFuncAttributeMaxDynamicSharedMemorySize, attn_smem);

    // 1) QKV projection: per batch C[1536, 2304] = w_qkv[1536,256] @ x[b][256,2304]
    gemm_kernel<<<dim3(N_TOK / 64, 1536 / 128, 2), 256>>>(
        w_qkv, x, qkv_ptr, nullptr, 1536, N_TOK, C_DIM,
        (long)C_DIM * N_TOK, (long)1536 * N_TOK);

    // 2) L2 normalize q and k rows over tokens (in place)
    normalize_kernel<<<2048, 256>>>();

    // 3) Fused attention -> g_att
    attn_kernel<<<dim3(N_TOK / 64, 16), 256, attn_smem>>>();

    // 4) Output projection + bias: y[b][256,2304] = w_proj @ att[b] + b_proj
    gemm_kernel<<<dim3(N_TOK / 64, C_DIM / 128, 2), 256>>>(
        w_proj, att_ptr, y, b_proj, C_DIM, N_TOK, HID,
        (long)HID * N_TOK, (long)C_DIM * N_TOK);
}

// round 7
// speedup vs baseline: 3.1519x; 2.4476x over previous
#include <cuda_runtime.h>
#include <cuda_bf16.h>
#include <math.h>
#include <stdint.h>

#define N_TOK 2304   // 48*48
#define C_DIM 256
#define HID   512    // 8 heads * 64

// Scratch (no allocations allowed): qkv = [b][1536][N], att out = [b][512][N]
__device__ float g_qkv[2][1536][N_TOK];
__device__ float g_att[2][512][N_TOK];

// ============================ helpers ======================================
__device__ __forceinline__ uint32_t smem_u32(const void* p) {
    uint32_t a;
    asm("{ .reg .u64 t; cvta.to.shared.u64 t, %1; cvt.u32.u64 %0, t; }" : "=r"(a) : "l"(p));
    return a;
}
// 128B-row swizzle (rows of 128B): 16B-unit index ^= (row & 7)
#define SW128(o) ((o) ^ (((o) >> 3) & 0x70))
// 256B-row swizzle (rows of 256B): 16B-unit index low3 ^= (row & 7)
#define SW256(o) ((o) ^ (((o) >> 4) & 0x70))

__device__ __forceinline__ void ldsm4(uint32_t* r, uint32_t addr) {
    asm volatile("ldmatrix.sync.aligned.m8n8.x4.shared.b16 {%0,%1,%2,%3}, [%4];"
                 : "=r"(r[0]), "=r"(r[1]), "=r"(r[2]), "=r"(r[3]) : "r"(addr));
}
__device__ __forceinline__ void mma_bf16(float* d, const uint32_t* a,
                                         uint32_t b0, uint32_t b1) {
    asm volatile(
        "mma.sync.aligned.m16n8k16.row.col.f32.bf16.bf16.f32 "
        "{%0,%1,%2,%3}, {%4,%5,%6,%7}, {%8,%9}, {%0,%1,%2,%3};"
        : "+f"(d[0]), "+f"(d[1]), "+f"(d[2]), "+f"(d[3])
        : "r"(a[0]), "r"(a[1]), "r"(a[2]), "r"(a[3]), "r"(b0), "r"(b1));
}
// split fp32 pair -> (bf16x2 hi word, bf16x2 lo word); first arg -> low half
__device__ __forceinline__ void split2(float a, float b, uint32_t& hi, uint32_t& lo) {
    __nv_bfloat162 h = __floats2bfloat162_rn(a, b);
    float ra = a - __bfloat162float(__low2bfloat16(h));
    float rb = b - __bfloat162float(__high2bfloat16(h));
    __nv_bfloat162 lw = __floats2bfloat162_rn(ra, rb);
    hi = *reinterpret_cast<uint32_t*>(&h);
    lo = *reinterpret_cast<uint32_t*>(&lw);
}

// ---- packed f32x2 helpers (scalar GEMMs) ----------------------------------
__device__ __forceinline__ unsigned long long pack2(float lo, float hi) {
    unsigned long long r;
    asm("mov.b64 %0, {%1,%2};" : "=l"(r) : "f"(lo), "f"(hi));
    return r;
}
__device__ __forceinline__ void unpack2(unsigned long long v, float& lo, float& hi) {
    asm("mov.b64 {%0,%1}, %2;" : "=f"(lo), "=f"(hi) : "l"(v));
}
__device__ __forceinline__ void ffma2(unsigned long long& d,
                                      unsigned long long a, unsigned long long b) {
    asm("fma.rn.f32x2 %0, %1, %2, %3;" : "=l"(d) : "l"(a), "l"(b), "l"(d));
}

// ---------------------------------------------------------------------------
// Tiled GEMM via packed FFMA2 (unchanged from R3)
// ---------------------------------------------------------------------------
__global__ __launch_bounds__(256) void gemm_kernel(
    const float* __restrict__ W,
    const float* __restrict__ Xb,
    float* __restrict__ Cb,
    const float* __restrict__ bias,
    int M, int N, int K,
    long xStride, long cStride)
{
    __shared__ unsigned long long Ws2[16][130];
    __shared__ float Xs[16][64];

    const float* X = Xb + (long)blockIdx.z * xStride;
    float* C = Cb + (long)blockIdx.z * cStride;
    const int by = blockIdx.y * 128;
    const int bx = blockIdx.x * 64;
    const int t  = threadIdx.x;
    const int tx = t & 15, ty = t >> 4;

    unsigned long long acc[8][2] = {};

    for (int kt = 0; kt < K; kt += 16) {
#pragma unroll
        for (int l = 0; l < 8; l++) {
            int idx = t + l * 256;
            int ii = idx >> 4, kk = idx & 15;
            float w = W[(long)(by + ii) * K + kt + kk];
            Ws2[kk][ii] = pack2(w, w);
        }
#pragma unroll
        for (int l = 0; l < 4; l++) {
            int idx = t + l * 256;
            int kk = idx >> 6, jj = idx & 63;
            Xs[kk][jj] = X[(long)(kt + kk) * N + bx + jj];
        }
        __syncthreads();
#pragma unroll
        for (int kk = 0; kk < 16; kk++) {
            unsigned long long a[8];
            *(ulonglong2*)&a[0] = *(const ulonglong2*)&Ws2[kk][ty * 8 + 0];
            *(ulonglong2*)&a[2] = *(const ulonglong2*)&Ws2[kk][ty * 8 + 2];
            *(ulonglong2*)&a[4] = *(const ulonglong2*)&Ws2[kk][ty * 8 + 4];
            *(ulonglong2*)&a[6] = *(const ulonglong2*)&Ws2[kk][ty * 8 + 6];
            ulonglong2 b = *(const ulonglong2*)&Xs[kk][tx * 4];
#pragma unroll
            for (int i = 0; i < 8; i++) {
                ffma2(acc[i][0], a[i], b.x);
                ffma2(acc[i][1], a[i], b.y);
            }
        }
        __syncthreads();
    }

#pragma unroll
    for (int i = 0; i < 8; i++) {
        int row = by + ty * 8 + i;
        float bb = bias ? bias[row] : 0.0f;
        float o0, o1, o2, o3;
        unpack2(acc[i][0], o0, o1);
        unpack2(acc[i][1], o2, o3);
        float4 o = make_float4(o0 + bb, o1 + bb, o2 + bb, o3 + bb);
        *(float4*)&C[(long)row * N + bx + tx * 4] = o;
    }
}

// ---------------------------------------------------------------------------
// L2 normalization (unchanged)
// ---------------------------------------------------------------------------
__global__ __launch_bounds__(256) void normalize_kernel()
{
    const int b   = blockIdx.x >> 10;
    const int row = blockIdx.x & 1023;
    float* p = g_qkv[b][row];
    const int t = threadIdx.x;

    float ss = 0.0f;
    for (int i = t; i < N_TOK; i += 256) { float v = p[i]; ss += v * v; }

    __shared__ float red[256];
    red[t] = ss;
    __syncthreads();
    for (int s = 128; s > 0; s >>= 1) {
        if (t < s) red[t] += red[t + s];
        __syncthreads();
    }
    __shared__ float sinv;
    if (t == 0) sinv = 1.0f / fmaxf(sqrtf(red[0]), 1e-12f);
    __syncthreads();
    const float inv = sinv;
    for (int i = t; i < N_TOK; i += 256) p[i] *= inv;
}

// ---------------------------------------------------------------------------
// Flash attention on mma.sync (HMMA) with split-bf16 3-pass precision.
// CTA = one (b,h), 128 q tokens; 8 warps x 16 q-rows. Loop kv tiles of 128.
//   S = Qhi Khi^T + Qhi Klo^T + Qlo Khi^T   (f32 frags)
//   P = exp(S), split hi/lo IN REGISTERS (C-frag == A-frag layout)
//   O += Phi Vhi + Phi Vlo + Plo Vhi
// smem: Q/K as [row][64d] bf16 (128B rows, SW128), V as [d][128m] (256B rows,
// SW256). Epilogue stages O in smem (reuse V) for coalesced stores.
// ---------------------------------------------------------------------------
#define AT_TILES (N_TOK / 128)
#define SM_QHI 0
#define SM_QLO 16384
#define SM_KHI 32768
#define SM_KLO 49152
#define SM_VHI 65536
#define SM_VLO 81920
#define SM_AT_TOTAL 98304

__global__ __launch_bounds__(256) void attn_mma_kernel()
{
    extern __shared__ char sm[];
    const uint32_t sb = smem_u32(sm);
    const int t = threadIdx.x;
    const int w = t >> 5, lane = t & 31;
    const int mt = lane >> 3, lr = lane & 7;      // ldmatrix matrix id / row
    const int bh = blockIdx.y, b = bh >> 3, h = bh & 7;
    const int nt = blockIdx.x * 128;
    const float* qg = g_qkv[b][h * 64];
    const float* kg = g_qkv[b][512 + h * 64];
    const float* vg = g_qkv[b][1024 + h * 64];

    // ---- Q tile -> smem (split bf16), rows n, 64 d (32 words) ----
#pragma unroll
    for (int i = 0; i < 16; i++) {
        int idx = t + i * 256;
        int dw = idx >> 7, n = idx & 127;
        float a = qg[(2 * dw) * N_TOK + nt + n];
        float c = qg[(2 * dw + 1) * N_TOK + nt + n];
        uint32_t hi, lo; split2(a, c, hi, lo);
        uint32_t off = SW128((uint32_t)(n * 128 + dw * 4));
        *(uint32_t*)(sm + SM_QHI + off) = hi;
        *(uint32_t*)(sm + SM_QLO + off) = lo;
    }
    __syncthreads();

    // ---- Q fragments (resident): 4 k-steps x (x4) x hi/lo ----
    uint32_t qh[4][4], ql[4][4];
#pragma unroll
    for (int ks = 0; ks < 4; ks++) {
        int row = w * 16 + lr + (mt & 1) * 8;
        int chunk = ks * 2 + (mt >> 1);
        uint32_t off = SW128((uint32_t)(row * 128 + chunk * 16));
        ldsm4(qh[ks], sb + SM_QHI + off);
        ldsm4(ql[ks], sb + SM_QLO + off);
    }

    float o[8][4];
#pragma unroll
    for (int j = 0; j < 8; j++) { o[j][0] = o[j][1] = o[j][2] = o[j][3] = 0.0f; }
    float den0 = 0.0f, den1 = 0.0f;

    for (int mtile = 0; mtile < AT_TILES; mtile++) {
        const int m0 = mtile * 128;
        __syncthreads();   // everyone done reading previous K/V smem

        // K tile: rows m (128B, SW128)
#pragma unroll
        for (int i = 0; i < 16; i++) {
            int idx = t + i * 256;
            int dw = idx >> 7, m = idx & 127;
            float a = kg[(2 * dw) * N_TOK + m0 + m];
            float c = kg[(2 * dw + 1) * N_TOK + m0 + m];
            uint32_t hi, lo; split2(a, c, hi, lo);
            uint32_t off = SW128((uint32_t)(m * 128 + dw * 4));
            *(uint32_t*)(sm + SM_KHI + off) = hi;
            *(uint32_t*)(sm + SM_KLO + off) = lo;
        }
        // V tile: rows d, 128 m (256B, SW256)
#pragma unroll
        for (int i = 0; i < 16; i++) {
            int idx = t + i * 256;
            int d = idx >> 6, mw = idx & 63;
            float2 v = *(const float2*)&vg[d * N_TOK + m0 + 2 * mw];
            uint32_t hi, lo; split2(v.x, v.y, hi, lo);
            uint32_t off = SW256((uint32_t)(d * 256 + mw * 4));
            *(uint32_t*)(sm + SM_VHI + off) = hi;
            *(uint32_t*)(sm + SM_VLO + off) = lo;
        }
        __syncthreads();

        // ---- 8 m-chunks of 16 ----
#pragma unroll
        for (int mc = 0; mc < 8; mc++) {
            // K fragments for this chunk (both m8-halves, 4 k-steps, hi/lo)
            uint32_t kh[4][4], kl[4][4];
#pragma unroll
            for (int ks = 0; ks < 4; ks++) {
                int row = mc * 16 + lr + (mt >> 1) * 8;
                int chunk = ks * 2 + (mt & 1);
                uint32_t off = SW128((uint32_t)(row * 128 + chunk * 16));
                ldsm4(kh[ks], sb + SM_KHI + off);
                ldsm4(kl[ks], sb + SM_KLO + off);
            }
            float s0[4] = {}, s1[4] = {};
#pragma unroll
            for (int ks = 0; ks < 4; ks++) {
                mma_bf16(s0, qh[ks], kh[ks][0], kh[ks][1]);
                mma_bf16(s1, qh[ks], kh[ks][2], kh[ks][3]);
            }
#pragma unroll
            for (int ks = 0; ks < 4; ks++) {
                mma_bf16(s0, qh[ks], kl[ks][0], kl[ks][1]);
                mma_bf16(s1, qh[ks], kl[ks][2], kl[ks][3]);
            }
#pragma unroll
            for (int ks = 0; ks < 4; ks++) {
                mma_bf16(s0, ql[ks], kh[ks][0], kh[ks][1]);
                mma_bf16(s1, ql[ks], kh[ks][2], kh[ks][3]);
            }

            // exp + split -> P A-fragments (in registers)
            float e00 = __expf(s0[0]), e01 = __expf(s0[1]);
            float e02 = __expf(s0[2]), e03 = __expf(s0[3]);
            float e10 = __expf(s1[0]), e11 = __expf(s1[1]);
            float e12 = __expf(s1[2]), e13 = __expf(s1[3]);
            den0 += e00 + e01 + e10 + e11;
            den1 += e02 + e03 + e12 + e13;
            uint32_t phi[4], plo[4];
            split2(e00, e01, phi[0], plo[0]);
            split2(e02, e03, phi[1], plo[1]);
            split2(e10, e11, phi[2], plo[2]);
            split2(e12, e13, phi[3], plo[3]);

            // PV: k-chunk = this m16; 4 dp pairs cover d=64
#pragma unroll
            for (int dp = 0; dp < 4; dp++) {
                int d = (dp * 2 + (mt >> 1)) * 8 + lr;
                uint32_t off = SW256((uint32_t)(d * 256 + mc * 32 + (mt & 1) * 16));
                uint32_t vh[4], vl[4];
                ldsm4(vh, sb + SM_VHI + off);
                ldsm4(vl, sb + SM_VLO + off);
                mma_bf16(o[dp * 2], phi, vh[0], vh[1]);
                mma_bf16(o[dp * 2 + 1], phi, vh[2], vh[3]);
                mma_bf16(o[dp * 2], phi, vl[0], vl[1]);
                mma_bf16(o[dp * 2 + 1], phi, vl[2], vl[3]);
                mma_bf16(o[dp * 2], plo, vh[0], vh[1]);
                mma_bf16(o[dp * 2 + 1], plo, vh[2], vh[3]);
            }
        }
    }

    // ---- softmax normalize (quad reduce) ----
    den0 += __shfl_xor_sync(0xFFFFFFFF, den0, 1);
    den0 += __shfl_xor_sync(0xFFFFFFFF, den0, 2);
    den1 += __shfl_xor_sync(0xFFFFFFFF, den1, 1);
    den1 += __shfl_xor_sync(0xFFFFFFFF, den1, 2);
    float inv0 = 1.0f / den0, inv1 = 1.0f / den1;

    // ---- stage O to smem [d][n] (reuse V region), then coalesced store ----
    __syncthreads();
    float* stage = (float*)(sm + SM_VHI);   // 64*128 f32 = 32KB
    int n0 = w * 16 + (lane >> 2);
#pragma unroll
    for (int j = 0; j < 8; j++) {
        int d0 = j * 8 + (lane & 3) * 2;
        stage[d0 * 128 + n0]           = o[j][0] * inv0;
        stage[(d0 + 1) * 128 + n0]     = o[j][1] * inv0;
        stage[d0 * 128 + n0 + 8]       = o[j][2] * inv1;
        stage[(d0 + 1) * 128 + n0 + 8] = o[j][3] * inv1;
    }
    __syncthreads();

    float* og = g_att[b][h * 64];
#pragma unroll
    for (int i = 0; i < 8; i++) {
        int idx = t + i * 256;           // float4 index
        int d = idx >> 5, n4 = idx & 31;
        *(float4*)&og[d * N_TOK + nt + n4 * 4] = *(float4*)&stage[d * 128 + n4 * 4];
    }
}

// ---------------------------------------------------------------------------
extern "C" void kernel_launch(void* const* d_in, const int* in_sizes, int n_in,
                              void* d_out, int out_size)
{
    const float* x      = (const float*)d_in[0];
    const float* w_qkv  = (const float*)d_in[1];
    const float* w_proj = (const float*)d_in[2];
    const float* b_proj = (const float*)d_in[3];
    float* y = (float*)d_out;

    float* qkv_ptr = nullptr;
    float* att_ptr = nullptr;
    cudaGetSymbolAddress((void**)&qkv_ptr, g_qkv);
    cudaGetSymbolAddress((void**)&att_ptr, g_att);

    cudaFuncSetAttribute(attn_mma_kernel, cudaFuncAttributeMaxDynamicSharedMemorySize,
                         SM_AT_TOTAL);

    // 1) QKV projection
    gemm_kernel<<<dim3(N_TOK / 64, 1536 / 128, 2), 256>>>(
        w_qkv, x, qkv_ptr, nullptr, 1536, N_TOK, C_DIM,
        (long)C_DIM * N_TOK, (long)1536 * N_TOK);

    // 2) L2 normalize q and k over tokens
    normalize_kernel<<<2048, 256>>>();

    // 3) HMMA flash attention
    attn_mma_kernel<<<dim3(N_TOK / 128, 16), 256, SM_AT_TOTAL>>>();

    // 4) Output projection + bias
    gemm_kernel<<<dim3(N_TOK / 64, C_DIM / 128, 2), 256>>>(
        w_proj, att_ptr, y, b_proj, C_DIM, N_TOK, HID,
        (long)HID * N_TOK, (long)C_DIM * N_TOK);
}

// round 10
// speedup vs baseline: 4.0194x; 1.2752x over previous
#include <cuda_runtime.h>
#include <cuda_bf16.h>
#include <math.h>
#include <stdint.h>

#define N_TOK 2304   // 48*48
#define C_DIM 256
#define HID   512    // 8 heads * 64

// Scratch (no allocations allowed): qkv = [b][1536][N], att out = [b][512][N]
__device__ float g_qkv[2][1536][N_TOK];
__device__ float g_att[2][512][N_TOK];

// ============================ helpers ======================================
__device__ __forceinline__ uint32_t smem_u32(const void* p) {
    uint32_t a;
    asm("{ .reg .u64 t; cvta.to.shared.u64 t, %1; cvt.u32.u64 %0, t; }" : "=r"(a) : "l"(p));
    return a;
}
// 128B-row swizzle (rows of 128B): 16B-unit index ^= (row & 7)
#define SW128(o) ((o) ^ (((o) >> 3) & 0x70))
// 256B-row swizzle (rows of 256B): 16B-unit index low3 ^= (row & 7)
#define SW256(o) ((o) ^ (((o) >> 4) & 0x70))

__device__ __forceinline__ void ldsm4(uint32_t* r, uint32_t addr) {
    asm volatile("ldmatrix.sync.aligned.m8n8.x4.shared.b16 {%0,%1,%2,%3}, [%4];"
                 : "=r"(r[0]), "=r"(r[1]), "=r"(r[2]), "=r"(r[3]) : "r"(addr));
}
__device__ __forceinline__ void mma_bf16(float* d, const uint32_t* a,
                                         uint32_t b0, uint32_t b1) {
    asm volatile(
        "mma.sync.aligned.m16n8k16.row.col.f32.bf16.bf16.f32 "
        "{%0,%1,%2,%3}, {%4,%5,%6,%7}, {%8,%9}, {%0,%1,%2,%3};"
        : "+f"(d[0]), "+f"(d[1]), "+f"(d[2]), "+f"(d[3])
        : "r"(a[0]), "r"(a[1]), "r"(a[2]), "r"(a[3]), "r"(b0), "r"(b1));
}
// split fp32 pair -> (bf16x2 hi word, bf16x2 lo word); first arg -> low half
__device__ __forceinline__ void split2(float a, float b, uint32_t& hi, uint32_t& lo) {
    __nv_bfloat162 h = __floats2bfloat162_rn(a, b);
    float ra = a - __bfloat162float(__low2bfloat16(h));
    float rb = b - __bfloat162float(__high2bfloat16(h));
    __nv_bfloat162 lw = __floats2bfloat162_rn(ra, rb);
    hi = *reinterpret_cast<uint32_t*>(&h);
    lo = *reinterpret_cast<uint32_t*>(&lw);
}

// ---------------------------------------------------------------------------
// HMMA split-bf16 GEMM: C[M,N] = W[M,K] @ X[K,N] (+bias), z = batch.
// Tile 128(M) x 128(N), K-tile 64, 256 threads (8 warps x 16 rows).
// 3-pass split precision: Whi*Xhi + Whi*Xlo + Wlo*Xhi, fp32 accum.
// A-frag path == attn Q loader; B-frag path == attn K loader (transposed).
// ---------------------------------------------------------------------------
#define SMG_WHI 0
#define SMG_WLO 16384
#define SMG_XHI 32768
#define SMG_XLO 49152
#define SMG_TOTAL 65536

__global__ __launch_bounds__(256) void gemm_hmma_kernel(
    const float* __restrict__ W,
    const float* __restrict__ Xb,
    float* __restrict__ Cb,
    const float* __restrict__ bias,
    int M, int N, int K,
    long xStride, long cStride)
{
    extern __shared__ char sm[];
    const uint32_t sb = smem_u32(sm);
    const float* X = Xb + (long)blockIdx.z * xStride;
    float* C = Cb + (long)blockIdx.z * cStride;
    const int by = blockIdx.y * 128;
    const int bx = blockIdx.x * 128;
    const int t = threadIdx.x;
    const int w = t >> 5, lane = t & 31;
    const int mt = lane >> 3, lr = lane & 7;

    float o[16][4];
#pragma unroll
    for (int j = 0; j < 16; j++) { o[j][0] = o[j][1] = o[j][2] = o[j][3] = 0.0f; }

    for (int kt = 0; kt < K; kt += 64) {
        __syncthreads();
        // W tile: rows m (k-contiguous), split bf16, SW128 rows of 128B
#pragma unroll
        for (int i = 0; i < 16; i++) {
            int idx = t + i * 256;
            int m = idx >> 5, kw = idx & 31;
            float2 v = *(const float2*)&W[(long)(by + m) * K + kt + 2 * kw];
            uint32_t hi, lo; split2(v.x, v.y, hi, lo);
            uint32_t off = SW128((uint32_t)(m * 128 + kw * 4));
            *(uint32_t*)(sm + SMG_WHI + off) = hi;
            *(uint32_t*)(sm + SMG_WLO + off) = lo;
        }
        // X tile: transpose to rows n (k-contiguous), split bf16
#pragma unroll
        for (int i = 0; i < 16; i++) {
            int idx = t + i * 256;
            int kw = idx >> 7, n = idx & 127;
            float a = X[(long)(kt + 2 * kw) * N + bx + n];
            float c = X[(long)(kt + 2 * kw + 1) * N + bx + n];
            uint32_t hi, lo; split2(a, c, hi, lo);
            uint32_t off = SW128((uint32_t)(n * 128 + kw * 4));
            *(uint32_t*)(sm + SMG_XHI + off) = hi;
            *(uint32_t*)(sm + SMG_XLO + off) = lo;
        }
        __syncthreads();

        // A fragments for this k-tile
        uint32_t ah[4][4], al[4][4];
#pragma unroll
        for (int ks = 0; ks < 4; ks++) {
            int row = w * 16 + lr + (mt & 1) * 8;
            int chunk = ks * 2 + (mt >> 1);
            uint32_t off = SW128((uint32_t)(row * 128 + chunk * 16));
            ldsm4(ah[ks], sb + SMG_WHI + off);
            ldsm4(al[ks], sb + SMG_WLO + off);
        }
        // 8 n-chunks of 16
#pragma unroll
        for (int mc = 0; mc < 8; mc++) {
            uint32_t bh[4][4], bl[4][4];
#pragma unroll
            for (int ks = 0; ks < 4; ks++) {
                int row = mc * 16 + lr + (mt >> 1) * 8;
                int chunk = ks * 2 + (mt & 1);
                uint32_t off = SW128((uint32_t)(row * 128 + chunk * 16));
                ldsm4(bh[ks], sb + SMG_XHI + off);
                ldsm4(bl[ks], sb + SMG_XLO + off);
            }
            float* s0 = o[2 * mc];
            float* s1 = o[2 * mc + 1];
#pragma unroll
            for (int ks = 0; ks < 4; ks++) {
                mma_bf16(s0, ah[ks], bh[ks][0], bh[ks][1]);
                mma_bf16(s1, ah[ks], bh[ks][2], bh[ks][3]);
            }
#pragma unroll
            for (int ks = 0; ks < 4; ks++) {
                mma_bf16(s0, ah[ks], bl[ks][0], bl[ks][1]);
                mma_bf16(s1, ah[ks], bl[ks][2], bl[ks][3]);
            }
#pragma unroll
            for (int ks = 0; ks < 4; ks++) {
                mma_bf16(s0, al[ks], bh[ks][0], bh[ks][1]);
                mma_bf16(s1, al[ks], bh[ks][2], bh[ks][3]);
            }
        }
    }

    // epilogue: fp32 stores (+bias)
    const int m0 = by + w * 16 + (lane >> 2);
    const float bb0 = bias ? bias[m0] : 0.0f;
    const float bb1 = bias ? bias[m0 + 8] : 0.0f;
#pragma unroll
    for (int mc = 0; mc < 8; mc++) {
        int n0 = bx + mc * 16 + (lane & 3) * 2;
        float2 v;
        v.x = o[2 * mc][0] + bb0; v.y = o[2 * mc][1] + bb0;
        *(float2*)&C[(long)m0 * N + n0] = v;
        v.x = o[2 * mc][2] + bb1; v.y = o[2 * mc][3] + bb1;
        *(float2*)&C[(long)(m0 + 8) * N + n0] = v;
        v.x = o[2 * mc + 1][0] + bb0; v.y = o[2 * mc + 1][1] + bb0;
        *(float2*)&C[(long)m0 * N + n0 + 8] = v;
        v.x = o[2 * mc + 1][2] + bb1; v.y = o[2 * mc + 1][3] + bb1;
        *(float2*)&C[(long)(m0 + 8) * N + n0 + 8] = v;
    }
}

// ---------------------------------------------------------------------------
// L2 normalization (unchanged)
// ---------------------------------------------------------------------------
__global__ __launch_bounds__(256) void normalize_kernel()
{
    const int b   = blockIdx.x >> 10;
    const int row = blockIdx.x & 1023;
    float* p = g_qkv[b][row];
    const int t = threadIdx.x;

    float ss = 0.0f;
    for (int i = t; i < N_TOK; i += 256) { float v = p[i]; ss += v * v; }

    __shared__ float red[256];
    red[t] = ss;
    __syncthreads();
    for (int s = 128; s > 0; s >>= 1) {
        if (t < s) red[t] += red[t + s];
        __syncthreads();
    }
    __shared__ float sinv;
    if (t == 0) sinv = 1.0f / fmaxf(sqrtf(red[0]), 1e-12f);
    __syncthreads();
    const float inv = sinv;
    for (int i = t; i < N_TOK; i += 256) p[i] *= inv;
}

// ---------------------------------------------------------------------------
// Flash attention on mma.sync (unchanged from R7)
// ---------------------------------------------------------------------------
#define AT_TILES (N_TOK / 128)
#define SM_QHI 0
#define SM_QLO 16384
#define SM_KHI 32768
#define SM_KLO 49152
#define SM_VHI 65536
#define SM_VLO 81920
#define SM_AT_TOTAL 98304

__global__ __launch_bounds__(256) void attn_mma_kernel()
{
    extern __shared__ char sm[];
    const uint32_t sb = smem_u32(sm);
    const int t = threadIdx.x;
    const int w = t >> 5, lane = t & 31;
    const int mt = lane >> 3, lr = lane & 7;
    const int bh = blockIdx.y, b = bh >> 3, h = bh & 7;
    const int nt = blockIdx.x * 128;
    const float* qg = g_qkv[b][h * 64];
    const float* kg = g_qkv[b][512 + h * 64];
    const float* vg = g_qkv[b][1024 + h * 64];

#pragma unroll
    for (int i = 0; i < 16; i++) {
        int idx = t + i * 256;
        int dw = idx >> 7, n = idx & 127;
        float a = qg[(2 * dw) * N_TOK + nt + n];
        float c = qg[(2 * dw + 1) * N_TOK + nt + n];
        uint32_t hi, lo; split2(a, c, hi, lo);
        uint32_t off = SW128((uint32_t)(n * 128 + dw * 4));
        *(uint32_t*)(sm + SM_QHI + off) = hi;
        *(uint32_t*)(sm + SM_QLO + off) = lo;
    }
    __syncthreads();

    uint32_t qh[4][4], ql[4][4];
#pragma unroll
    for (int ks = 0; ks < 4; ks++) {
        int row = w * 16 + lr + (mt & 1) * 8;
        int chunk = ks * 2 + (mt >> 1);
        uint32_t off = SW128((uint32_t)(row * 128 + chunk * 16));
        ldsm4(qh[ks], sb + SM_QHI + off);
        ldsm4(ql[ks], sb + SM_QLO + off);
    }

    float o[8][4];
#pragma unroll
    for (int j = 0; j < 8; j++) { o[j][0] = o[j][1] = o[j][2] = o[j][3] = 0.0f; }
    float den0 = 0.0f, den1 = 0.0f;

    for (int mtile = 0; mtile < AT_TILES; mtile++) {
        const int m0 = mtile * 128;
        __syncthreads();

#pragma unroll
        for (int i = 0; i < 16; i++) {
            int idx = t + i * 256;
            int dw = idx >> 7, m = idx & 127;
            float a = kg[(2 * dw) * N_TOK + m0 + m];
            float c = kg[(2 * dw + 1) * N_TOK + m0 + m];
            uint32_t hi, lo; split2(a, c, hi, lo);
            uint32_t off = SW128((uint32_t)(m * 128 + dw * 4));
            *(uint32_t*)(sm + SM_KHI + off) = hi;
            *(uint32_t*)(sm + SM_KLO + off) = lo;
        }
#pragma unroll
        for (int i = 0; i < 16; i++) {
            int idx = t + i * 256;
            int d = idx >> 6, mw = idx & 63;
            float2 v = *(const float2*)&vg[d * N_TOK + m0 + 2 * mw];
            uint32_t hi, lo; split2(v.x, v.y, hi, lo);
            uint32_t off = SW256((uint32_t)(d * 256 + mw * 4));
            *(uint32_t*)(sm + SM_VHI + off) = hi;
            *(uint32_t*)(sm + SM_VLO + off) = lo;
        }
        __syncthreads();

#pragma unroll
        for (int mc = 0; mc < 8; mc++) {
            uint32_t kh[4][4], kl[4][4];
#pragma unroll
            for (int ks = 0; ks < 4; ks++) {
                int row = mc * 16 + lr + (mt >> 1) * 8;
                int chunk = ks * 2 + (mt & 1);
                uint32_t off = SW128((uint32_t)(row * 128 + chunk * 16));
                ldsm4(kh[ks], sb + SM_KHI + off);
                ldsm4(kl[ks], sb + SM_KLO + off);
            }
            float s0[4] = {}, s1[4] = {};
#pragma unroll
            for (int ks = 0; ks < 4; ks++) {
                mma_bf16(s0, qh[ks], kh[ks][0], kh[ks][1]);
                mma_bf16(s1, qh[ks], kh[ks][2], kh[ks][3]);
            }
#pragma unroll
            for (int ks = 0; ks < 4; ks++) {
                mma_bf16(s0, qh[ks], kl[ks][0], kl[ks][1]);
                mma_bf16(s1, qh[ks], kl[ks][2], kl[ks][3]);
            }
#pragma unroll
            for (int ks = 0; ks < 4; ks++) {
                mma_bf16(s0, ql[ks], kh[ks][0], kh[ks][1]);
                mma_bf16(s1, ql[ks], kh[ks][2], kh[ks][3]);
            }

            float e00 = __expf(s0[0]), e01 = __expf(s0[1]);
            float e02 = __expf(s0[2]), e03 = __expf(s0[3]);
            float e10 = __expf(s1[0]), e11 = __expf(s1[1]);
            float e12 = __expf(s1[2]), e13 = __expf(s1[3]);
            den0 += e00 + e01 + e10 + e11;
            den1 += e02 + e03 + e12 + e13;
            uint32_t phi[4], plo[4];
            split2(e00, e01, phi[0], plo[0]);
            split2(e02, e03, phi[1], plo[1]);
            split2(e10, e11, phi[2], plo[2]);
            split2(e12, e13, phi[3], plo[3]);

#pragma unroll
            for (int dp = 0; dp < 4; dp++) {
                int d = (dp * 2 + (mt >> 1)) * 8 + lr;
                uint32_t off = SW256((uint32_t)(d * 256 + mc * 32 + (mt & 1) * 16));
                uint32_t vh[4], vl[4];
                ldsm4(vh, sb + SM_VHI + off);
                ldsm4(vl, sb + SM_VLO + off);
                mma_bf16(o[dp * 2], phi, vh[0], vh[1]);
                mma_bf16(o[dp * 2 + 1], phi, vh[2], vh[3]);
                mma_bf16(o[dp * 2], phi, vl[0], vl[1]);
                mma_bf16(o[dp * 2 + 1], phi, vl[2], vl[3]);
                mma_bf16(o[dp * 2], plo, vh[0], vh[1]);
                mma_bf16(o[dp * 2 + 1], plo, vh[2], vh[3]);
            }
        }
    }

    den0 += __shfl_xor_sync(0xFFFFFFFF, den0, 1);
    den0 += __shfl_xor_sync(0xFFFFFFFF, den0, 2);
    den1 += __shfl_xor_sync(0xFFFFFFFF, den1, 1);
    den1 += __shfl_xor_sync(0xFFFFFFFF, den1, 2);
    float inv0 = 1.0f / den0, inv1 = 1.0f / den1;

    __syncthreads();
    float* stage = (float*)(sm + SM_VHI);
    int n0 = w * 16 + (lane >> 2);
#pragma unroll
    for (int j = 0; j < 8; j++) {
        int d0 = j * 8 + (lane & 3) * 2;
        stage[d0 * 128 + n0]           = o[j][0] * inv0;
        stage[(d0 + 1) * 128 + n0]     = o[j][1] * inv0;
        stage[d0 * 128 + n0 + 8]       = o[j][2] * inv1;
        stage[(d0 + 1) * 128 + n0 + 8] = o[j][3] * inv1;
    }
    __syncthreads();

    float* og = g_att[b][h * 64];
#pragma unroll
    for (int i = 0; i < 8; i++) {
        int idx = t + i * 256;
        int d = idx >> 5, n4 = idx & 31;
        *(float4*)&og[d * N_TOK + nt + n4 * 4] = *(float4*)&stage[d * 128 + n4 * 4];
    }
}

// ---------------------------------------------------------------------------
extern "C" void kernel_launch(void* const* d_in, const int* in_sizes, int n_in,
                              void* d_out, int out_size)
{
    const float* x      = (const float*)d_in[0];
    const float* w_qkv  = (const float*)d_in[1];
    const float* w_proj = (const float*)d_in[2];
    const float* b_proj = (const float*)d_in[3];
    float* y = (float*)d_out;

    float* qkv_ptr = nullptr;
    float* att_ptr = nullptr;
    cudaGetSymbolAddress((void**)&qkv_ptr, g_qkv);
    cudaGetSymbolAddress((void**)&att_ptr, g_att);

    cudaFuncSetAttribute(gemm_hmma_kernel, cudaFuncAttributeMaxDynamicSharedMemorySize,
                         SMG_TOTAL);
    cudaFuncSetAttribute(attn_mma_kernel, cudaFuncAttributeMaxDynamicSharedMemorySize,
                         SM_AT_TOTAL);

    // 1) QKV projection: [1536,2304] = w_qkv[1536,256] @ x[b][256,2304]
    gemm_hmma_kernel<<<dim3(N_TOK / 128, 1536 / 128, 2), 256, SMG_TOTAL>>>(
        w_qkv, x, qkv_ptr, nullptr, 1536, N_TOK, C_DIM,
        (long)C_DIM * N_TOK, (long)1536 * N_TOK);

    // 2) L2 normalize q and k over tokens
    normalize_kernel<<<2048, 256>>>();

    // 3) HMMA flash attention
    attn_mma_kernel<<<dim3(N_TOK / 128, 16), 256, SM_AT_TOTAL>>>();

    // 4) Output projection + bias: [256,2304] = w_proj[256,512] @ att[b][512,2304]
    gemm_hmma_kernel<<<dim3(N_TOK / 128, C_DIM / 128, 2), 256, SMG_TOTAL>>>(
        w_proj, att_ptr, y, b_proj, C_DIM, N_TOK, HID,
        (long)HID * N_TOK, (long)C_DIM * N_TOK);
}

// round 13
// speedup vs baseline: 4.2800x; 1.0649x over previous
#include <cuda_runtime.h>
#include <cuda_bf16.h>
#include <math.h>
#include <stdint.h>

#define N_TOK 2304   // 48*48
#define C_DIM 256
#define HID   512    // 8 heads * 64

// Scratch (no allocations allowed)
__device__ float g_qkv[2][1536][N_TOK];                    // fp32 qkv (GEMM out)
__device__ float g_inv[2][1024];                           // q/k row inv-norms
__device__ __nv_bfloat16 g_qk_bf[2][2][8][2][N_TOK][64];   // [b][q/k][h][hi/lo][tok][d]
__device__ __nv_bfloat16 g_v_bf[2][8][2][64][N_TOK];       // [b][h][hi/lo][d][tok]
__device__ __nv_bfloat16 g_att_bf[2][2][N_TOK][HID];       // [b][hi/lo][tok][hid]

// ============================ helpers ======================================
__device__ __forceinline__ uint32_t smem_u32(const void* p) {
    uint32_t a;
    asm("{ .reg .u64 t; cvta.to.shared.u64 t, %1; cvt.u32.u64 %0, t; }" : "=r"(a) : "l"(p));
    return a;
}
#define SW128(o) ((o) ^ (((o) >> 3) & 0x70))
#define SW256(o) ((o) ^ (((o) >> 4) & 0x70))

__device__ __forceinline__ void ldsm4(uint32_t* r, uint32_t addr) {
    asm volatile("ldmatrix.sync.aligned.m8n8.x4.shared.b16 {%0,%1,%2,%3}, [%4];"
                 : "=r"(r[0]), "=r"(r[1]), "=r"(r[2]), "=r"(r[3]) : "r"(addr));
}
__device__ __forceinline__ void mma_bf16(float* d, const uint32_t* a,
                                         uint32_t b0, uint32_t b1) {
    asm volatile(
        "mma.sync.aligned.m16n8k16.row.col.f32.bf16.bf16.f32 "
        "{%0,%1,%2,%3}, {%4,%5,%6,%7}, {%8,%9}, {%0,%1,%2,%3};"
        : "+f"(d[0]), "+f"(d[1]), "+f"(d[2]), "+f"(d[3])
        : "r"(a[0]), "r"(a[1]), "r"(a[2]), "r"(a[3]), "r"(b0), "r"(b1));
}
// split fp32 pair -> (bf16x2 hi word, bf16x2 lo word); first arg -> low half
__device__ __forceinline__ void split2(float a, float b, uint32_t& hi, uint32_t& lo) {
    __nv_bfloat162 h = __floats2bfloat162_rn(a, b);
    float ra = a - __bfloat162float(__low2bfloat16(h));
    float rb = b - __bfloat162float(__high2bfloat16(h));
    __nv_bfloat162 lw = __floats2bfloat162_rn(ra, rb);
    hi = *reinterpret_cast<uint32_t*>(&h);
    lo = *reinterpret_cast<uint32_t*>(&lw);
}

// ---------------------------------------------------------------------------
// HMMA split-bf16 GEMM (fp32 X): C = W @ X (+bias).  Used for QKV projection.
// Tile 128x128, K-tile 64, 256 threads; 3-pass Whi*Xhi + Whi*Xlo + Wlo*Xhi.
// ---------------------------------------------------------------------------
#define SMG_WHI 0
#define SMG_WLO 16384
#define SMG_XHI 32768
#define SMG_XLO 49152
#define SMG_TOTAL 65536

__global__ __launch_bounds__(256) void gemm_hmma_kernel(
    const float* __restrict__ W,
    const float* __restrict__ Xb,
    float* __restrict__ Cb,
    const float* __restrict__ bias,
    int M, int N, int K,
    long xStride, long cStride)
{
    extern __shared__ char sm[];
    const uint32_t sb = smem_u32(sm);
    const float* X = Xb + (long)blockIdx.z * xStride;
    float* C = Cb + (long)blockIdx.z * cStride;
    const int by = blockIdx.y * 128;
    const int bx = blockIdx.x * 128;
    const int t = threadIdx.x;
    const int w = t >> 5, lane = t & 31;
    const int mt = lane >> 3, lr = lane & 7;

    float o[16][4];
#pragma unroll
    for (int j = 0; j < 16; j++) { o[j][0] = o[j][1] = o[j][2] = o[j][3] = 0.0f; }

    for (int kt = 0; kt < K; kt += 64) {
        __syncthreads();
#pragma unroll
        for (int i = 0; i < 16; i++) {
            int idx = t + i * 256;
            int m = idx >> 5, kw = idx & 31;
            float2 v = *(const float2*)&W[(long)(by + m) * K + kt + 2 * kw];
            uint32_t hi, lo; split2(v.x, v.y, hi, lo);
            uint32_t off = SW128((uint32_t)(m * 128 + kw * 4));
            *(uint32_t*)(sm + SMG_WHI + off) = hi;
            *(uint32_t*)(sm + SMG_WLO + off) = lo;
        }
#pragma unroll
        for (int i = 0; i < 16; i++) {
            int idx = t + i * 256;
            int kw = idx >> 7, n = idx & 127;
            float a = X[(long)(kt + 2 * kw) * N + bx + n];
            float c = X[(long)(kt + 2 * kw + 1) * N + bx + n];
            uint32_t hi, lo; split2(a, c, hi, lo);
            uint32_t off = SW128((uint32_t)(n * 128 + kw * 4));
            *(uint32_t*)(sm + SMG_XHI + off) = hi;
            *(uint32_t*)(sm + SMG_XLO + off) = lo;
        }
        __syncthreads();

        uint32_t ah[4][4], al[4][4];
#pragma unroll
        for (int ks = 0; ks < 4; ks++) {
            int row = w * 16 + lr + (mt & 1) * 8;
            int chunk = ks * 2 + (mt >> 1);
            uint32_t off = SW128((uint32_t)(row * 128 + chunk * 16));
            ldsm4(ah[ks], sb + SMG_WHI + off);
            ldsm4(al[ks], sb + SMG_WLO + off);
        }
#pragma unroll
        for (int mc = 0; mc < 8; mc++) {
            uint32_t bh[4][4], bl[4][4];
#pragma unroll
            for (int ks = 0; ks < 4; ks++) {
                int row = mc * 16 + lr + (mt >> 1) * 8;
                int chunk = ks * 2 + (mt & 1);
                uint32_t off = SW128((uint32_t)(row * 128 + chunk * 16));
                ldsm4(bh[ks], sb + SMG_XHI + off);
                ldsm4(bl[ks], sb + SMG_XLO + off);
            }
            float* s0 = o[2 * mc];
            float* s1 = o[2 * mc + 1];
#pragma unroll
            for (int ks = 0; ks < 4; ks++) {
                mma_bf16(s0, ah[ks], bh[ks][0], bh[ks][1]);
                mma_bf16(s1, ah[ks], bh[ks][2], bh[ks][3]);
            }
#pragma unroll
            for (int ks = 0; ks < 4; ks++) {
                mma_bf16(s0, ah[ks], bl[ks][0], bl[ks][1]);
                mma_bf16(s1, ah[ks], bl[ks][2], bl[ks][3]);
            }
#pragma unroll
            for (int ks = 0; ks < 4; ks++) {
                mma_bf16(s0, al[ks], bh[ks][0], bh[ks][1]);
                mma_bf16(s1, al[ks], bh[ks][2], bh[ks][3]);
            }
        }
    }

    const int m0 = by + w * 16 + (lane >> 2);
    const float bb0 = bias ? bias[m0] : 0.0f;
    const float bb1 = bias ? bias[m0 + 8] : 0.0f;
#pragma unroll
    for (int mc = 0; mc < 8; mc++) {
        int n0 = bx + mc * 16 + (lane & 3) * 2;
        float2 v;
        v.x = o[2 * mc][0] + bb0; v.y = o[2 * mc][1] + bb0;
        *(float2*)&C[(long)m0 * N + n0] = v;
        v.x = o[2 * mc][2] + bb1; v.y = o[2 * mc][3] + bb1;
        *(float2*)&C[(long)(m0 + 8) * N + n0] = v;
        v.x = o[2 * mc + 1][0] + bb0; v.y = o[2 * mc + 1][1] + bb0;
        *(float2*)&C[(long)m0 * N + n0 + 8] = v;
        v.x = o[2 * mc + 1][2] + bb1; v.y = o[2 * mc + 1][3] + bb1;
        *(float2*)&C[(long)(m0 + 8) * N + n0 + 8] = v;
    }
}

// ---------------------------------------------------------------------------
// HMMA split-bf16 GEMM, X pre-split bf16 planes [tok][K].  Used for proj.
// ---------------------------------------------------------------------------
__global__ __launch_bounds__(256) void gemm_hmma_bfx_kernel(
    const float* __restrict__ W,
    const uint4* __restrict__ Xbf,      // plane pairs per batch
    float* __restrict__ Cb,
    const float* __restrict__ bias,
    int M, int N, int K,
    long xPlanePairStride, long cStride)
{
    extern __shared__ char sm[];
    const uint32_t sb = smem_u32(sm);
    const uint4* xhi = Xbf + (long)blockIdx.z * xPlanePairStride;
    const uint4* xlo = xhi + xPlanePairStride / 2;
    float* C = Cb + (long)blockIdx.z * cStride;
    const int by = blockIdx.y * 128;
    const int bx = blockIdx.x * 128;
    const int t = threadIdx.x;
    const int w = t >> 5, lane = t & 31;
    const int mt = lane >> 3, lr = lane & 7;
    const int rowU4 = K >> 3;           // uint4 per X row

    float o[16][4];
#pragma unroll
    for (int j = 0; j < 16; j++) { o[j][0] = o[j][1] = o[j][2] = o[j][3] = 0.0f; }

    for (int kt = 0; kt < K; kt += 64) {
        __syncthreads();
#pragma unroll
        for (int i = 0; i < 16; i++) {
            int idx = t + i * 256;
            int m = idx >> 5, kw = idx & 31;
            float2 v = *(const float2*)&W[(long)(by + m) * K + kt + 2 * kw];
            uint32_t hi, lo; split2(v.x, v.y, hi, lo);
            uint32_t off = SW128((uint32_t)(m * 128 + kw * 4));
            *(uint32_t*)(sm + SMG_WHI + off) = hi;
            *(uint32_t*)(sm + SMG_WLO + off) = lo;
        }
        // X: pure copy of pre-split planes (rows n=tok, k contiguous)
#pragma unroll
        for (int i = 0; i < 4; i++) {
            int idx = t + i * 256;
            int row = idx >> 3, c = idx & 7;
            long src = (long)(bx + row) * rowU4 + (kt >> 3) + c;
            uint32_t off = SW128((uint32_t)(row * 128 + c * 16));
            *(uint4*)(sm + SMG_XHI + off) = xhi[src];
            *(uint4*)(sm + SMG_XLO + off) = xlo[src];
        }
        __syncthreads();

        uint32_t ah[4][4], al[4][4];
#pragma unroll
        for (int ks = 0; ks < 4; ks++) {
            int row = w * 16 + lr + (mt & 1) * 8;
            int chunk = ks * 2 + (mt >> 1);
            uint32_t off = SW128((uint32_t)(row * 128 + chunk * 16));
            ldsm4(ah[ks], sb + SMG_WHI + off);
            ldsm4(al[ks], sb + SMG_WLO + off);
        }
#pragma unroll
        for (int mc = 0; mc < 8; mc++) {
            uint32_t bh[4][4], bl[4][4];
#pragma unroll
            for (int ks = 0; ks < 4; ks++) {
                int row = mc * 16 + lr + (mt >> 1) * 8;
                int chunk = ks * 2 + (mt & 1);
                uint32_t off = SW128((uint32_t)(row * 128 + chunk * 16));
                ldsm4(bh[ks], sb + SMG_XHI + off);
                ldsm4(bl[ks], sb + SMG_XLO + off);
            }
            float* s0 = o[2 * mc];
            float* s1 = o[2 * mc + 1];
#pragma unroll
            for (int ks = 0; ks < 4; ks++) {
                mma_bf16(s0, ah[ks], bh[ks][0], bh[ks][1]);
                mma_bf16(s1, ah[ks], bh[ks][2], bh[ks][3]);
            }
#pragma unroll
            for (int ks = 0; ks < 4; ks++) {
                mma_bf16(s0, ah[ks], bl[ks][0], bl[ks][1]);
                mma_bf16(s1, ah[ks], bl[ks][2], bl[ks][3]);
            }
#pragma unroll
            for (int ks = 0; ks < 4; ks++) {
                mma_bf16(s0, al[ks], bh[ks][0], bh[ks][1]);
                mma_bf16(s1, al[ks], bh[ks][2], bh[ks][3]);
            }
        }
    }

    const int m0 = by + w * 16 + (lane >> 2);
    const float bb0 = bias ? bias[m0] : 0.0f;
    const float bb1 = bias ? bias[m0 + 8] : 0.0f;
#pragma unroll
    for (int mc = 0; mc < 8; mc++) {
        int n0 = bx + mc * 16 + (lane & 3) * 2;
        float2 v;
        v.x = o[2 * mc][0] + bb0; v.y = o[2 * mc][1] + bb0;
        *(float2*)&C[(long)m0 * N + n0] = v;
        v.x = o[2 * mc][2] + bb1; v.y = o[2 * mc][3] + bb1;
        *(float2*)&C[(long)(m0 + 8) * N + n0] = v;
        v.x = o[2 * mc + 1][0] + bb0; v.y = o[2 * mc + 1][1] + bb0;
        *(float2*)&C[(long)m0 * N + n0 + 8] = v;
        v.x = o[2 * mc + 1][2] + bb1; v.y = o[2 * mc + 1][3] + bb1;
        *(float2*)&C[(long)(m0 + 8) * N + n0 + 8] = v;
    }
}

// ---------------------------------------------------------------------------
// Per-(b, q/k, h, d) L2 inv-norm over tokens (reduce only, no rewrite).
// ---------------------------------------------------------------------------
__global__ __launch_bounds__(256) void norm_reduce_kernel()
{
    const int b   = blockIdx.x >> 10;
    const int row = blockIdx.x & 1023;
    const float* p = g_qkv[b][row];
    const int t = threadIdx.x;

    float ss = 0.0f;
    for (int i = t; i < N_TOK; i += 256) { float v = p[i]; ss += v * v; }

    __shared__ float red[256];
    red[t] = ss;
    __syncthreads();
    for (int s = 128; s > 0; s >>= 1) {
        if (t < s) red[t] += red[t + s];
        __syncthreads();
    }
    if (t == 0) g_inv[b][row] = 1.0f / fmaxf(sqrtf(red[0]), 1e-12f);
}

// ---------------------------------------------------------------------------
// Convert: q/k -> normalized bf16 hi/lo planes [tok][64d] (transposed);
//          v   -> bf16 hi/lo planes [d][tok].
// Blocks [0,576): q/k tile (b, qk, h, 128-token tile) = 2*2*8*18.
// Blocks [576,1600): v rows = 2*512.
// ---------------------------------------------------------------------------
__global__ __launch_bounds__(256) void convert_kernel()
{
    const int t = threadIdx.x;
    if (blockIdx.x < 576) {
        __shared__ float tile[64][129];
        __shared__ float inv_s[64];
        int a = blockIdx.x;
        int tt = a % 18; a /= 18;        // a in [0,32)
        int h = a & 7; a >>= 3;          // a in [0,4)
        int qk = a & 1;
        int b = a >> 1;                  // b in [0,2)
        const int rowbase = qk * 512 + h * 64;
        if (t < 64) inv_s[t] = g_inv[b][rowbase + t];
        __syncthreads();
#pragma unroll
        for (int i = 0; i < 32; i++) {
            int idx = t + i * 256;
            int tok = idx & 127, d = idx >> 7;
            tile[d][tok] = g_qkv[b][rowbase + d][tt * 128 + tok] * inv_s[d];
        }
        __syncthreads();
        uint32_t* dhi = (uint32_t*)g_qk_bf[b][qk][h][0];
        uint32_t* dlo = (uint32_t*)g_qk_bf[b][qk][h][1];
#pragma unroll
        for (int i = 0; i < 16; i++) {
            int idx = t + i * 256;
            int tok = idx >> 5, dw = idx & 31;
            uint32_t hi, lo;
            split2(tile[2 * dw][tok], tile[2 * dw + 1][tok], hi, lo);
            dhi[(tt * 128 + tok) * 32 + dw] = hi;
            dlo[(tt * 128 + tok) * 32 + dw] = lo;
        }
    } else {
        int a = blockIdx.x - 576;        // [0,1024)
        int b = a >> 9, r = a & 511;
        int h = r >> 6, d = r & 63;
        const float2* src = (const float2*)g_qkv[b][1024 + r];
        uint32_t* dhi = (uint32_t*)g_v_bf[b][h][0][d];
        uint32_t* dlo = (uint32_t*)g_v_bf[b][h][1][d];
#pragma unroll
        for (int i = 0; i < 5; i++) {
            int idx = t + i * 256;
            if (idx < N_TOK / 2) {
                float2 v = src[idx];
                uint32_t hi, lo; split2(v.x, v.y, hi, lo);
                dhi[idx] = hi;
                dlo[idx] = lo;
            }
        }
    }
}

// ---------------------------------------------------------------------------
// Flash attention on mma.sync; operands pre-split bf16 (pure-copy loaders).
// Epilogue writes O directly as bf16 hi/lo planes (proj GEMM input).
// ---------------------------------------------------------------------------
#define AT_TILES (N_TOK / 128)
#define SM_QHI 0
#define SM_QLO 16384
#define SM_KHI 32768
#define SM_KLO 49152
#define SM_VHI 65536
#define SM_VLO 81920
#define SM_AT_TOTAL 98304

__global__ __launch_bounds__(256) void attn_mma_kernel()
{
    extern __shared__ char sm[];
    const uint32_t sb = smem_u32(sm);
    const int t = threadIdx.x;
    const int w = t >> 5, lane = t & 31;
    const int mt = lane >> 3, lr = lane & 7;
    const int bh = blockIdx.y, b = bh >> 3, h = bh & 7;
    const int nt = blockIdx.x * 128;

    const uint4* qhi = (const uint4*)g_qk_bf[b][0][h][0];
    const uint4* qlo = (const uint4*)g_qk_bf[b][0][h][1];
    const uint4* khi = (const uint4*)g_qk_bf[b][1][h][0];
    const uint4* klo = (const uint4*)g_qk_bf[b][1][h][1];
    const uint4* vhi = (const uint4*)g_v_bf[b][h][0];
    const uint4* vlo = (const uint4*)g_v_bf[b][h][1];

    // Q tile: rows [tok][64d] = 8 uint4, SW128
#pragma unroll
    for (int i = 0; i < 4; i++) {
        int idx = t + i * 256;
        int row = idx >> 3, c = idx & 7;
        long src = (long)(nt + row) * 8 + c;
        uint32_t off = SW128((uint32_t)(row * 128 + c * 16));
        *(uint4*)(sm + SM_QHI + off) = qhi[src];
        *(uint4*)(sm + SM_QLO + off) = qlo[src];
    }
    __syncthreads();

    uint32_t qh[4][4], ql[4][4];
#pragma unroll
    for (int ks = 0; ks < 4; ks++) {
        int row = w * 16 + lr + (mt & 1) * 8;
        int chunk = ks * 2 + (mt >> 1);
        uint32_t off = SW128((uint32_t)(row * 128 + chunk * 16));
        ldsm4(qh[ks], sb + SM_QHI + off);
        ldsm4(ql[ks], sb + SM_QLO + off);
    }

    float o[8][4];
#pragma unroll
    for (int j = 0; j < 8; j++) { o[j][0] = o[j][1] = o[j][2] = o[j][3] = 0.0f; }
    float den0 = 0.0f, den1 = 0.0f;

    for (int mtile = 0; mtile < AT_TILES; mtile++) {
        const int m0 = mtile * 128;
        __syncthreads();

        // K tile copy: rows m, 8 uint4 each
#pragma unroll
        for (int i = 0; i < 4; i++) {
            int idx = t + i * 256;
            int row = idx >> 3, c = idx & 7;
            long src = (long)(m0 + row) * 8 + c;
            uint32_t off = SW128((uint32_t)(row * 128 + c * 16));
            *(uint4*)(sm + SM_KHI + off) = khi[src];
            *(uint4*)(sm + SM_KLO + off) = klo[src];
        }
        // V tile copy: rows d, 16 uint4 each (128 tokens)
#pragma unroll
        for (int i = 0; i < 4; i++) {
            int idx = t + i * 256;
            int d = idx >> 4, c = idx & 15;
            long src = (long)d * (N_TOK / 8) + (m0 >> 3) + c;
            uint32_t off = SW256((uint32_t)(d * 256 + c * 16));
            *(uint4*)(sm + SM_VHI + off) = vhi[src];
            *(uint4*)(sm + SM_VLO + off) = vlo[src];
        }
        __syncthreads();

#pragma unroll
        for (int mc = 0; mc < 8; mc++) {
            uint32_t kh[4][4], kl[4][4];
#pragma unroll
            for (int ks = 0; ks < 4; ks++) {
                int row = mc * 16 + lr + (mt >> 1) * 8;
                int chunk = ks * 2 + (mt & 1);
                uint32_t off = SW128((uint32_t)(row * 128 + chunk * 16));
                ldsm4(kh[ks], sb + SM_KHI + off);
                ldsm4(kl[ks], sb + SM_KLO + off);
            }
            float s0[4] = {}, s1[4] = {};
#pragma unroll
            for (int ks = 0; ks < 4; ks++) {
                mma_bf16(s0, qh[ks], kh[ks][0], kh[ks][1]);
                mma_bf16(s1, qh[ks], kh[ks][2], kh[ks][3]);
            }
#pragma unroll
            for (int ks = 0; ks < 4; ks++) {
                mma_bf16(s0, qh[ks], kl[ks][0], kl[ks][1]);
                mma_bf16(s1, qh[ks], kl[ks][2], kl[ks][3]);
            }
#pragma unroll
            for (int ks = 0; ks < 4; ks++) {
                mma_bf16(s0, ql[ks], kh[ks][0], kh[ks][1]);
                mma_bf16(s1, ql[ks], kh[ks][2], kh[ks][3]);
            }

            float e00 = __expf(s0[0]), e01 = __expf(s0[1]);
            float e02 = __expf(s0[2]), e03 = __expf(s0[3]);
            float e10 = __expf(s1[0]), e11 = __expf(s1[1]);
            float e12 = __expf(s1[2]), e13 = __expf(s1[3]);
            den0 += e00 + e01 + e10 + e11;
            den1 += e02 + e03 + e12 + e13;
            uint32_t phi[4], plo[4];
            split2(e00, e01, phi[0], plo[0]);
            split2(e02, e03, phi[1], plo[1]);
            split2(e10, e11, phi[2], plo[2]);
            split2(e12, e13, phi[3], plo[3]);

#pragma unroll
            for (int dp = 0; dp < 4; dp++) {
                int d = (dp * 2 + (mt >> 1)) * 8 + lr;
                uint32_t off = SW256((uint32_t)(d * 256 + mc * 32 + (mt & 1) * 16));
                uint32_t vh[4], vl[4];
                ldsm4(vh, sb + SM_VHI + off);
                ldsm4(vl, sb + SM_VLO + off);
                mma_bf16(o[dp * 2], phi, vh[0], vh[1]);
                mma_bf16(o[dp * 2 + 1], phi, vh[2], vh[3]);
                mma_bf16(o[dp * 2], phi, vl[0], vl[1]);
                mma_bf16(o[dp * 2 + 1], phi, vl[2], vl[3]);
                mma_bf16(o[dp * 2], plo, vh[0], vh[1]);
                mma_bf16(o[dp * 2 + 1], plo, vh[2], vh[3]);
            }
        }
    }

    den0 += __shfl_xor_sync(0xFFFFFFFF, den0, 1);
    den0 += __shfl_xor_sync(0xFFFFFFFF, den0, 2);
    den1 += __shfl_xor_sync(0xFFFFFFFF, den1, 1);
    den1 += __shfl_xor_sync(0xFFFFFFFF, den1, 2);
    float inv0 = 1.0f / den0, inv1 = 1.0f / den1;

    // direct bf16 hi/lo epilogue: word dw covers d=(2dw,2dw+1); c-frag pairs match
    uint32_t* atthi = (uint32_t*)g_att_bf[b][0];   // rows of 256 words (512 bf16)
    uint32_t* attlo = (uint32_t*)g_att_bf[b][1];
    const int tok0 = w * 16 + (lane >> 2);
#pragma unroll
    for (int j = 0; j < 8; j++) {
        int dw = j * 4 + (lane & 3);
        uint32_t hi, lo;
        split2(o[j][0] * inv0, o[j][1] * inv0, hi, lo);
        long w0 = (long)(nt + tok0) * 256 + h * 32 + dw;
        atthi[w0] = hi; attlo[w0] = lo;
        split2(o[j][2] * inv1, o[j][3] * inv1, hi, lo);
        long w1 = (long)(nt + tok0 + 8) * 256 + h * 32 + dw;
        atthi[w1] = hi; attlo[w1] = lo;
    }
}

// ---------------------------------------------------------------------------
extern "C" void kernel_launch(void* const* d_in, const int* in_sizes, int n_in,
                              void* d_out, int out_size)
{
    const float* x      = (const float*)d_in[0];
    const float* w_qkv  = (const float*)d_in[1];
    const float* w_proj = (const float*)d_in[2];
    const float* b_proj = (const float*)d_in[3];
    float* y = (float*)d_out;

    float* qkv_ptr = nullptr;
    void* attbf_ptr = nullptr;
    cudaGetSymbolAddress((void**)&qkv_ptr, g_qkv);
    cudaGetSymbolAddress(&attbf_ptr, g_att_bf);

    cudaFuncSetAttribute(gemm_hmma_kernel, cudaFuncAttributeMaxDynamicSharedMemorySize,
                         SMG_TOTAL);
    cudaFuncSetAttribute(gemm_hmma_bfx_kernel, cudaFuncAttributeMaxDynamicSharedMemorySize,
                         SMG_TOTAL);
    cudaFuncSetAttribute(attn_mma_kernel, cudaFuncAttributeMaxDynamicSharedMemorySize,
                         SM_AT_TOTAL);

    // 1) QKV projection (fp32 X)
    gemm_hmma_kernel<<<dim3(N_TOK / 128, 1536 / 128, 2), 256, SMG_TOTAL>>>(
        w_qkv, x, qkv_ptr, nullptr, 1536, N_TOK, C_DIM,
        (long)C_DIM * N_TOK, (long)1536 * N_TOK);

    // 2) inv-norms for q/k rows
    norm_reduce_kernel<<<2048, 256>>>();

    // 3) pre-split conversion (q/k transpose+normalize, v elementwise)
    convert_kernel<<<1600, 256>>>();

    // 4) flash attention (bf16 operands) -> g_att_bf planes
    attn_mma_kernel<<<dim3(N_TOK / 128, 16), 256, SM_AT_TOTAL>>>();

    // 5) output projection from bf16 planes
    gemm_hmma_bfx_kernel<<<dim3(N_TOK / 128, C_DIM / 128, 2), 256, SMG_TOTAL>>>(
        w_proj, (const uint4*)attbf_ptr, y, b_proj, C_DIM, N_TOK, HID,
        (long)2 * N_TOK * HID / 8, (long)C_DIM * N_TOK);
}

// round 16
// speedup vs baseline: 5.3061x; 1.2398x over previous
#include <cuda_runtime.h>
#include <cuda_bf16.h>
#include <math.h>
#include <stdint.h>

#define N_TOK 2304   // 48*48
#define C_DIM 256
#define HID   512    // 8 heads * 64

// Scratch (no allocations allowed)
__device__ float g_qkv[2][1536][N_TOK];                    // fp32 qkv (GEMM out)
__device__ float g_inv[2][1024];                           // q/k row inv-norms
__device__ __nv_bfloat16 g_qk_bf[2][2][8][N_TOK][64];      // [b][q/k][h][tok][d] (hi only)
__device__ __nv_bfloat16 g_v_bf[2][8][2][64][N_TOK];       // [b][h][hi/lo][d][tok]
__device__ __nv_bfloat16 g_att_bf[2][2][N_TOK][HID];       // [b][hi/lo][tok][hid]

// ============================ helpers ======================================
__device__ __forceinline__ uint32_t smem_u32(const void* p) {
    uint32_t a;
    asm("{ .reg .u64 t; cvta.to.shared.u64 t, %1; cvt.u32.u64 %0, t; }" : "=r"(a) : "l"(p));
    return a;
}
#define SW128(o) ((o) ^ (((o) >> 3) & 0x70))
#define SW256(o) ((o) ^ (((o) >> 4) & 0x70))

__device__ __forceinline__ void ldsm4(uint32_t* r, uint32_t addr) {
    asm volatile("ldmatrix.sync.aligned.m8n8.x4.shared.b16 {%0,%1,%2,%3}, [%4];"
                 : "=r"(r[0]), "=r"(r[1]), "=r"(r[2]), "=r"(r[3]) : "r"(addr));
}
__device__ __forceinline__ void mma_bf16(float* d, const uint32_t* a,
                                         uint32_t b0, uint32_t b1) {
    asm volatile(
        "mma.sync.aligned.m16n8k16.row.col.f32.bf16.bf16.f32 "
        "{%0,%1,%2,%3}, {%4,%5,%6,%7}, {%8,%9}, {%0,%1,%2,%3};"
        : "+f"(d[0]), "+f"(d[1]), "+f"(d[2]), "+f"(d[3])
        : "r"(a[0]), "r"(a[1]), "r"(a[2]), "r"(a[3]), "r"(b0), "r"(b1));
}
// split fp32 pair -> (bf16x2 hi word, bf16x2 lo word); first arg -> low half
__device__ __forceinline__ void split2(float a, float b, uint32_t& hi, uint32_t& lo) {
    __nv_bfloat162 h = __floats2bfloat162_rn(a, b);
    float ra = a - __bfloat162float(__low2bfloat16(h));
    float rb = b - __bfloat162float(__high2bfloat16(h));
    __nv_bfloat162 lw = __floats2bfloat162_rn(ra, rb);
    hi = *reinterpret_cast<uint32_t*>(&h);
    lo = *reinterpret_cast<uint32_t*>(&lw);
}
__device__ __forceinline__ uint32_t pack_bf2(float a, float b) {
    __nv_bfloat162 h = __floats2bfloat162_rn(a, b);
    return *reinterpret_cast<uint32_t*>(&h);
}

// ---------------------------------------------------------------------------
// HMMA split-bf16 GEMM (fp32 X): C = W @ X (+bias).  Used for QKV projection.
// Tile 128x128, K-tile 64, 256 threads; 3-pass Whi*Xhi + Whi*Xlo + Wlo*Xhi.
// ---------------------------------------------------------------------------
#define SMG_WHI 0
#define SMG_WLO 16384
#define SMG_XHI 32768
#define SMG_XLO 49152
#define SMG_TOTAL 65536

__global__ __launch_bounds__(256) void gemm_hmma_kernel(
    const float* __restrict__ W,
    const float* __restrict__ Xb,
    float* __restrict__ Cb,
    const float* __restrict__ bias,
    int M, int N, int K,
    long xStride, long cStride)
{
    extern __shared__ char sm[];
    const uint32_t sb = smem_u32(sm);
    const float* X = Xb + (long)blockIdx.z * xStride;
    float* C = Cb + (long)blockIdx.z * cStride;
    const int by = blockIdx.y * 128;
    const int bx = blockIdx.x * 128;
    const int t = threadIdx.x;
    const int w = t >> 5, lane = t & 31;
    const int mt = lane >> 3, lr = lane & 7;

    float o[16][4];
#pragma unroll
    for (int j = 0; j < 16; j++) { o[j][0] = o[j][1] = o[j][2] = o[j][3] = 0.0f; }

    for (int kt = 0; kt < K; kt += 64) {
        __syncthreads();
#pragma unroll
        for (int i = 0; i < 16; i++) {
            int idx = t + i * 256;
            int m = idx >> 5, kw = idx & 31;
            float2 v = *(const float2*)&W[(long)(by + m) * K + kt + 2 * kw];
            uint32_t hi, lo; split2(v.x, v.y, hi, lo);
            uint32_t off = SW128((uint32_t)(m * 128 + kw * 4));
            *(uint32_t*)(sm + SMG_WHI + off) = hi;
            *(uint32_t*)(sm + SMG_WLO + off) = lo;
        }
#pragma unroll
        for (int i = 0; i < 16; i++) {
            int idx = t + i * 256;
            int kw = idx >> 7, n = idx & 127;
            float a = X[(long)(kt + 2 * kw) * N + bx + n];
            float c = X[(long)(kt + 2 * kw + 1) * N + bx + n];
            uint32_t hi, lo; split2(a, c, hi, lo);
            uint32_t off = SW128((uint32_t)(n * 128 + kw * 4));
            *(uint32_t*)(sm + SMG_XHI + off) = hi;
            *(uint32_t*)(sm + SMG_XLO + off) = lo;
        }
        __syncthreads();

        uint32_t ah[4][4], al[4][4];
#pragma unroll
        for (int ks = 0; ks < 4; ks++) {
            int row = w * 16 + lr + (mt & 1) * 8;
            int chunk = ks * 2 + (mt >> 1);
            uint32_t off = SW128((uint32_t)(row * 128 + chunk * 16));
            ldsm4(ah[ks], sb + SMG_WHI + off);
            ldsm4(al[ks], sb + SMG_WLO + off);
        }
#pragma unroll
        for (int mc = 0; mc < 8; mc++) {
            uint32_t bh[4][4], bl[4][4];
#pragma unroll
            for (int ks = 0; ks < 4; ks++) {
                int row = mc * 16 + lr + (mt >> 1) * 8;
                int chunk = ks * 2 + (mt & 1);
                uint32_t off = SW128((uint32_t)(row * 128 + chunk * 16));
                ldsm4(bh[ks], sb + SMG_XHI + off);
                ldsm4(bl[ks], sb + SMG_XLO + off);
            }
            float* s0 = o[2 * mc];
            float* s1 = o[2 * mc + 1];
#pragma unroll
            for (int ks = 0; ks < 4; ks++) {
                mma_bf16(s0, ah[ks], bh[ks][0], bh[ks][1]);
                mma_bf16(s1, ah[ks], bh[ks][2], bh[ks][3]);
            }
#pragma unroll
            for (int ks = 0; ks < 4; ks++) {
                mma_bf16(s0, ah[ks], bl[ks][0], bl[ks][1]);
                mma_bf16(s1, ah[ks], bl[ks][2], bl[ks][3]);
            }
#pragma unroll
            for (int ks = 0; ks < 4; ks++) {
                mma_bf16(s0, al[ks], bh[ks][0], bh[ks][1]);
                mma_bf16(s1, al[ks], bh[ks][2], bh[ks][3]);
            }
        }
    }

    const int m0 = by + w * 16 + (lane >> 2);
    const float bb0 = bias ? bias[m0] : 0.0f;
    const float bb1 = bias ? bias[m0 + 8] : 0.0f;
#pragma unroll
    for (int mc = 0; mc < 8; mc++) {
        int n0 = bx + mc * 16 + (lane & 3) * 2;
        float2 v;
        v.x = o[2 * mc][0] + bb0; v.y = o[2 * mc][1] + bb0;
        *(float2*)&C[(long)m0 * N + n0] = v;
        v.x = o[2 * mc][2] + bb1; v.y = o[2 * mc][3] + bb1;
        *(float2*)&C[(long)(m0 + 8) * N + n0] = v;
        v.x = o[2 * mc + 1][0] + bb0; v.y = o[2 * mc + 1][1] + bb0;
        *(float2*)&C[(long)m0 * N + n0 + 8] = v;
        v.x = o[2 * mc + 1][2] + bb1; v.y = o[2 * mc + 1][3] + bb1;
        *(float2*)&C[(long)(m0 + 8) * N + n0 + 8] = v;
    }
}

// ---------------------------------------------------------------------------
// HMMA split-bf16 GEMM, X pre-split bf16 planes [tok][K].  Used for proj.
// ---------------------------------------------------------------------------
__global__ __launch_bounds__(256) void gemm_hmma_bfx_kernel(
    const float* __restrict__ W,
    const uint4* __restrict__ Xbf,      // plane pairs per batch
    float* __restrict__ Cb,
    const float* __restrict__ bias,
    int M, int N, int K,
    long xPlanePairStride, long cStride)
{
    extern __shared__ char sm[];
    const uint32_t sb = smem_u32(sm);
    const uint4* xhi = Xbf + (long)blockIdx.z * xPlanePairStride;
    const uint4* xlo = xhi + xPlanePairStride / 2;
    float* C = Cb + (long)blockIdx.z * cStride;
    const int by = blockIdx.y * 128;
    const int bx = blockIdx.x * 128;
    const int t = threadIdx.x;
    const int w = t >> 5, lane = t & 31;
    const int mt = lane >> 3, lr = lane & 7;
    const int rowU4 = K >> 3;           // uint4 per X row

    float o[16][4];
#pragma unroll
    for (int j = 0; j < 16; j++) { o[j][0] = o[j][1] = o[j][2] = o[j][3] = 0.0f; }

    for (int kt = 0; kt < K; kt += 64) {
        __syncthreads();
#pragma unroll
        for (int i = 0; i < 16; i++) {
            int idx = t + i * 256;
            int m = idx >> 5, kw = idx & 31;
            float2 v = *(const float2*)&W[(long)(by + m) * K + kt + 2 * kw];
            uint32_t hi, lo; split2(v.x, v.y, hi, lo);
            uint32_t off = SW128((uint32_t)(m * 128 + kw * 4));
            *(uint32_t*)(sm + SMG_WHI + off) = hi;
            *(uint32_t*)(sm + SMG_WLO + off) = lo;
        }
        // X: pure copy of pre-split planes (rows n=tok, k contiguous)
#pragma unroll
        for (int i = 0; i < 4; i++) {
            int idx = t + i * 256;
            int row = idx >> 3, c = idx & 7;
            long src = (long)(bx + row) * rowU4 + (kt >> 3) + c;
            uint32_t off = SW128((uint32_t)(row * 128 + c * 16));
            *(uint4*)(sm + SMG_XHI + off) = xhi[src];
            *(uint4*)(sm + SMG_XLO + off) = xlo[src];
        }
        __syncthreads();

        uint32_t ah[4][4], al[4][4];
#pragma unroll
        for (int ks = 0; ks < 4; ks++) {
            int row = w * 16 + lr + (mt & 1) * 8;
            int chunk = ks * 2 + (mt >> 1);
            uint32_t off = SW128((uint32_t)(row * 128 + chunk * 16));
            ldsm4(ah[ks], sb + SMG_WHI + off);
            ldsm4(al[ks], sb + SMG_WLO + off);
        }
#pragma unroll
        for (int mc = 0; mc < 8; mc++) {
            uint32_t bh[4][4], bl[4][4];
#pragma unroll
            for (int ks = 0; ks < 4; ks++) {
                int row = mc * 16 + lr + (mt >> 1) * 8;
                int chunk = ks * 2 + (mt & 1);
                uint32_t off = SW128((uint32_t)(row * 128 + chunk * 16));
                ldsm4(bh[ks], sb + SMG_XHI + off);
                ldsm4(bl[ks], sb + SMG_XLO + off);
            }
            float* s0 = o[2 * mc];
            float* s1 = o[2 * mc + 1];
#pragma unroll
            for (int ks = 0; ks < 4; ks++) {
                mma_bf16(s0, ah[ks], bh[ks][0], bh[ks][1]);
                mma_bf16(s1, ah[ks], bh[ks][2], bh[ks][3]);
            }
#pragma unroll
            for (int ks = 0; ks < 4; ks++) {
                mma_bf16(s0, ah[ks], bl[ks][0], bl[ks][1]);
                mma_bf16(s1, ah[ks], bl[ks][2], bl[ks][3]);
            }
#pragma unroll
            for (int ks = 0; ks < 4; ks++) {
                mma_bf16(s0, al[ks], bh[ks][0], bh[ks][1]);
                mma_bf16(s1, al[ks], bh[ks][2], bh[ks][3]);
            }
        }
    }

    const int m0 = by + w * 16 + (lane >> 2);
    const float bb0 = bias ? bias[m0] : 0.0f;
    const float bb1 = bias ? bias[m0 + 8] : 0.0f;
#pragma unroll
    for (int mc = 0; mc < 8; mc++) {
        int n0 = bx + mc * 16 + (lane & 3) * 2;
        float2 v;
        v.x = o[2 * mc][0] + bb0; v.y = o[2 * mc][1] + bb0;
        *(float2*)&C[(long)m0 * N + n0] = v;
        v.x = o[2 * mc][2] + bb1; v.y = o[2 * mc][3] + bb1;
        *(float2*)&C[(long)(m0 + 8) * N + n0] = v;
        v.x = o[2 * mc + 1][0] + bb0; v.y = o[2 * mc + 1][1] + bb0;
        *(float2*)&C[(long)m0 * N + n0 + 8] = v;
        v.x = o[2 * mc + 1][2] + bb1; v.y = o[2 * mc + 1][3] + bb1;
        *(float2*)&C[(long)(m0 + 8) * N + n0 + 8] = v;
    }
}

// ---------------------------------------------------------------------------
// Per-(b, q/k, h, d) L2 inv-norm over tokens (reduce only, no rewrite).
// ---------------------------------------------------------------------------
__global__ __launch_bounds__(256) void norm_reduce_kernel()
{
    const int b   = blockIdx.x >> 10;
    const int row = blockIdx.x & 1023;
    const float* p = g_qkv[b][row];
    const int t = threadIdx.x;

    float ss = 0.0f;
    for (int i = t; i < N_TOK; i += 256) { float v = p[i]; ss += v * v; }

    __shared__ float red[256];
    red[t] = ss;
    __syncthreads();
    for (int s = 128; s > 0; s >>= 1) {
        if (t < s) red[t] += red[t + s];
        __syncthreads();
    }
    if (t == 0) g_inv[b][row] = 1.0f / fmaxf(sqrtf(red[0]), 1e-12f);
}

// ---------------------------------------------------------------------------
// Convert: q/k -> normalized bf16 (hi only) planes [tok][64d] (transposed);
//          v   -> bf16 hi/lo planes [d][tok].
// Blocks [0,576): q/k tile (b, qk, h, 128-token tile) = 2*2*8*18.
// Blocks [576,1600): v rows = 2*512.
// ---------------------------------------------------------------------------
__global__ __launch_bounds__(256) void convert_kernel()
{
    const int t = threadIdx.x;
    if (blockIdx.x < 576) {
        __shared__ float tile[64][129];
        __shared__ float inv_s[64];
        int a = blockIdx.x;
        int tt = a % 18; a /= 18;        // a in [0,32)
        int h = a & 7; a >>= 3;          // a in [0,4)
        int qk = a & 1;
        int b = a >> 1;                  // b in [0,2)
        const int rowbase = qk * 512 + h * 64;
        if (t < 64) inv_s[t] = g_inv[b][rowbase + t];
        __syncthreads();
#pragma unroll
        for (int i = 0; i < 32; i++) {
            int idx = t + i * 256;
            int tok = idx & 127, d = idx >> 7;
            tile[d][tok] = g_qkv[b][rowbase + d][tt * 128 + tok] * inv_s[d];
        }
        __syncthreads();
        uint32_t* dhi = (uint32_t*)g_qk_bf[b][qk][h];
#pragma unroll
        for (int i = 0; i < 16; i++) {
            int idx = t + i * 256;
            int tok = idx >> 5, dw = idx & 31;
            dhi[(tt * 128 + tok) * 32 + dw] =
                pack_bf2(tile[2 * dw][tok], tile[2 * dw + 1][tok]);
        }
    } else {
        int a = blockIdx.x - 576;        // [0,1024)
        int b = a >> 9, r = a & 511;
        int h = r >> 6, d = r & 63;
        const float2* src = (const float2*)g_qkv[b][1024 + r];
        uint32_t* dhi = (uint32_t*)g_v_bf[b][h][0][d];
        uint32_t* dlo = (uint32_t*)g_v_bf[b][h][1][d];
#pragma unroll
        for (int i = 0; i < 5; i++) {
            int idx = t + i * 256;
            if (idx < N_TOK / 2) {
                float2 v = src[idx];
                uint32_t hi, lo; split2(v.x, v.y, hi, lo);
                dhi[idx] = hi;
                dlo[idx] = lo;
            }
        }
    }
}

// ---------------------------------------------------------------------------
// Flash attention on mma.sync. QK^T single-pass bf16 (logits ~1e-2: q,k are
// L2-normalized over 2304 tokens, so hi*hi alone is accurate to ~2e-5 abs).
// PV stays 3-pass split (needed for 1e-3). 64KB smem, 2 CTAs/SM target.
// ---------------------------------------------------------------------------
#define AT_TILES (N_TOK / 128)
#define SM_QHI 0
#define SM_KHI 16384
#define SM_VHI 32768
#define SM_VLO 49152
#define SM_AT_TOTAL 65536

__global__ __launch_bounds__(256, 2) void attn_mma_kernel()
{
    extern __shared__ char sm[];
    const uint32_t sb = smem_u32(sm);
    const int t = threadIdx.x;
    const int w = t >> 5, lane = t & 31;
    const int mt = lane >> 3, lr = lane & 7;
    const int bh = blockIdx.y, b = bh >> 3, h = bh & 7;
    const int nt = blockIdx.x * 128;

    const uint4* qhi = (const uint4*)g_qk_bf[b][0][h];
    const uint4* khi = (const uint4*)g_qk_bf[b][1][h];
    const uint4* vhi = (const uint4*)g_v_bf[b][h][0];
    const uint4* vlo = (const uint4*)g_v_bf[b][h][1];

    // Q tile: rows [tok][64d] = 8 uint4, SW128
#pragma unroll
    for (int i = 0; i < 4; i++) {
        int idx = t + i * 256;
        int row = idx >> 3, c = idx & 7;
        long src = (long)(nt + row) * 8 + c;
        uint32_t off = SW128((uint32_t)(row * 128 + c * 16));
        *(uint4*)(sm + SM_QHI + off) = qhi[src];
    }
    __syncthreads();

    uint32_t qh[4][4];
#pragma unroll
    for (int ks = 0; ks < 4; ks++) {
        int row = w * 16 + lr + (mt & 1) * 8;
        int chunk = ks * 2 + (mt >> 1);
        uint32_t off = SW128((uint32_t)(row * 128 + chunk * 16));
        ldsm4(qh[ks], sb + SM_QHI + off);
    }

    float o[8][4];
#pragma unroll
    for (int j = 0; j < 8; j++) { o[j][0] = o[j][1] = o[j][2] = o[j][3] = 0.0f; }
    float den0 = 0.0f, den1 = 0.0f;

    for (int mtile = 0; mtile < AT_TILES; mtile++) {
        const int m0 = mtile * 128;
        __syncthreads();

        // K tile copy: rows m, 8 uint4 each
#pragma unroll
        for (int i = 0; i < 4; i++) {
            int idx = t + i * 256;
            int row = idx >> 3, c = idx & 7;
            long src = (long)(m0 + row) * 8 + c;
            uint32_t off = SW128((uint32_t)(row * 128 + c * 16));
            *(uint4*)(sm + SM_KHI + off) = khi[src];
        }
        // V tile copy: rows d, 16 uint4 each (128 tokens)
#pragma unroll
        for (int i = 0; i < 4; i++) {
            int idx = t + i * 256;
            int d = idx >> 4, c = idx & 15;
            long src = (long)d * (N_TOK / 8) + (m0 >> 3) + c;
            uint32_t off = SW256((uint32_t)(d * 256 + c * 16));
            *(uint4*)(sm + SM_VHI + off) = vhi[src];
            *(uint4*)(sm + SM_VLO + off) = vlo[src];
        }
        __syncthreads();

#pragma unroll
        for (int mc = 0; mc < 8; mc++) {
            uint32_t kh[4][4];
#pragma unroll
            for (int ks = 0; ks < 4; ks++) {
                int row = mc * 16 + lr + (mt >> 1) * 8;
                int chunk = ks * 2 + (mt & 1);
                uint32_t off = SW128((uint32_t)(row * 128 + chunk * 16));
                ldsm4(kh[ks], sb + SM_KHI + off);
            }
            float s0[4] = {}, s1[4] = {};
#pragma unroll
            for (int ks = 0; ks < 4; ks++) {
                mma_bf16(s0, qh[ks], kh[ks][0], kh[ks][1]);
                mma_bf16(s1, qh[ks], kh[ks][2], kh[ks][3]);
            }

            float e00 = __expf(s0[0]), e01 = __expf(s0[1]);
            float e02 = __expf(s0[2]), e03 = __expf(s0[3]);
            float e10 = __expf(s1[0]), e11 = __expf(s1[1]);
            float e12 = __expf(s1[2]), e13 = __expf(s1[3]);
            den0 += e00 + e01 + e10 + e11;
            den1 += e02 + e03 + e12 + e13;
            uint32_t phi[4], plo[4];
            split2(e00, e01, phi[0], plo[0]);
            split2(e02, e03, phi[1], plo[1]);
            split2(e10, e11, phi[2], plo[2]);
            split2(e12, e13, phi[3], plo[3]);

#pragma unroll
            for (int dp = 0; dp < 4; dp++) {
                int d = (dp * 2 + (mt >> 1)) * 8 + lr;
                uint32_t off = SW256((uint32_t)(d * 256 + mc * 32 + (mt & 1) * 16));
                uint32_t vh[4], vl[4];
                ldsm4(vh, sb + SM_VHI + off);
                ldsm4(vl, sb + SM_VLO + off);
                mma_bf16(o[dp * 2], phi, vh[0], vh[1]);
                mma_bf16(o[dp * 2 + 1], phi, vh[2], vh[3]);
                mma_bf16(o[dp * 2], phi, vl[0], vl[1]);
                mma_bf16(o[dp * 2 + 1], phi, vl[2], vl[3]);
                mma_bf16(o[dp * 2], plo, vh[0], vh[1]);
                mma_bf16(o[dp * 2 + 1], plo, vh[2], vh[3]);
            }
        }
    }

    den0 += __shfl_xor_sync(0xFFFFFFFF, den0, 1);
    den0 += __shfl_xor_sync(0xFFFFFFFF, den0, 2);
    den1 += __shfl_xor_sync(0xFFFFFFFF, den1, 1);
    den1 += __shfl_xor_sync(0xFFFFFFFF, den1, 2);
    float inv0 = 1.0f / den0, inv1 = 1.0f / den1;

    // direct bf16 hi/lo epilogue: word dw covers d=(2dw,2dw+1); c-frag pairs match
    uint32_t* atthi = (uint32_t*)g_att_bf[b][0];   // rows of 256 words (512 bf16)
    uint32_t* attlo = (uint32_t*)g_att_bf[b][1];
    const int tok0 = w * 16 + (lane >> 2);
#pragma unroll
    for (int j = 0; j < 8; j++) {
        int dw = j * 4 + (lane & 3);
        uint32_t hi, lo;
        split2(o[j][0] * inv0, o[j][1] * inv0, hi, lo);
        long w0 = (long)(nt + tok0) * 256 + h * 32 + dw;
        atthi[w0] = hi; attlo[w0] = lo;
        split2(o[j][2] * inv1, o[j][3] * inv1, hi, lo);
        long w1 = (long)(nt + tok0 + 8) * 256 + h * 32 + dw;
        atthi[w1] = hi; attlo[w1] = lo;
    }
}

// ---------------------------------------------------------------------------
extern "C" void kernel_launch(void* const* d_in, const int* in_sizes, int n_in,
                              void* d_out, int out_size)
{
    const float* x      = (const float*)d_in[0];
    const float* w_qkv  = (const float*)d_in[1];
    const float* w_proj = (const float*)d_in[2];
    const float* b_proj = (const float*)d_in[3];
    float* y = (float*)d_out;

    float* qkv_ptr = nullptr;
    void* attbf_ptr = nullptr;
    cudaGetSymbolAddress((void**)&qkv_ptr, g_qkv);
    cudaGetSymbolAddress(&attbf_ptr, g_att_bf);

    cudaFuncSetAttribute(gemm_hmma_kernel, cudaFuncAttributeMaxDynamicSharedMemorySize,
                         SMG_TOTAL);
    cudaFuncSetAttribute(gemm_hmma_bfx_kernel, cudaFuncAttributeMaxDynamicSharedMemorySize,
                         SMG_TOTAL);
    cudaFuncSetAttribute(attn_mma_kernel, cudaFuncAttributeMaxDynamicSharedMemorySize,
                         SM_AT_TOTAL);

    // 1) QKV projection (fp32 X)
    gemm_hmma_kernel<<<dim3(N_TOK / 128, 1536 / 128, 2), 256, SMG_TOTAL>>>(
        w_qkv, x, qkv_ptr, nullptr, 1536, N_TOK, C_DIM,
        (long)C_DIM * N_TOK, (long)1536 * N_TOK);

    // 2) inv-norms for q/k rows
    norm_reduce_kernel<<<2048, 256>>>();

    // 3) pre-split conversion (q/k transpose+normalize hi-only, v hi/lo)
    convert_kernel<<<1600, 256>>>();

    // 4) flash attention (bf16 operands) -> g_att_bf planes
    attn_mma_kernel<<<dim3(N_TOK / 128, 16), 256, SM_AT_TOTAL>>>();

    // 5) output projection from bf16 planes
    gemm_hmma_bfx_kernel<<<dim3(N_TOK / 128, C_DIM / 128, 2), 256, SMG_TOTAL>>>(
        w_proj, (const uint4*)attbf_ptr, y, b_proj, C_DIM, N_TOK, HID,
        (long)2 * N_TOK * HID / 8, (long)C_DIM * N_TOK);
}